// round 10
// baseline (speedup 1.0000x reference)
#include <cuda_runtime.h>
#include <cuda_fp16.h>
#include <cstdint>
#include <math.h>

#define DMODEL 1024
#define NHEADS 16
#define DK     64
#define BATCH  4
#define SEQ    2048
#define MTOT   (BATCH*SEQ)   // 8192

#define QSCALE 0.1803368801111204f   // 0.125 * log2(e)

// ---------------- device scratch (allocation-free) ----------------
__device__ __half g_Qh[(size_t)MTOT * DMODEL];  // [B*H][S][DK]
__device__ __half g_Ql[(size_t)MTOT * DMODEL];
__device__ __half g_Kh[(size_t)MTOT * DMODEL];  // hi only
__device__ __half g_Vh[(size_t)MTOT * DMODEL];  // hi only
__device__ __half g_xh[(size_t)MTOT * DMODEL];
__device__ __half g_xl[(size_t)MTOT * DMODEL];
__device__ __half g_Wh[(size_t)4 * DMODEL * DMODEL];   // weights hi only
__device__ __half g_ah[(size_t)MTOT * DMODEL];  // attn out (hi only) [B,S,H*DK]

// ---------------- helpers ----------------
__device__ __forceinline__ uint32_t smem_u32(const void* p) {
    uint32_t a;
    asm("{ .reg .u64 t; cvta.to.shared.u64 t, %1; cvt.u32.u64 %0, t; }" : "=r"(a) : "l"(p));
    return a;
}
__device__ __forceinline__ uint32_t swz(uint32_t o) { return o ^ ((o >> 3) & 0x70); }

__device__ __forceinline__ void cp16(uint32_t dst, const void* src) {
    asm volatile("cp.async.cg.shared.global [%0], [%1], 16;" :: "r"(dst), "l"(src));
}
#define CP_COMMIT() asm volatile("cp.async.commit_group;" ::: "memory")
#define CP_WAIT0()  asm volatile("cp.async.wait_group 0;" ::: "memory")
#define CP_WAIT1()  asm volatile("cp.async.wait_group 1;" ::: "memory")
#define CP_WAIT2()  asm volatile("cp.async.wait_group 2;" ::: "memory")

__device__ __forceinline__ void ldsm4(uint32_t* r, uint32_t a) {
    asm volatile("ldmatrix.sync.aligned.m8n8.x4.shared.b16 {%0,%1,%2,%3}, [%4];"
                 : "=r"(r[0]), "=r"(r[1]), "=r"(r[2]), "=r"(r[3]) : "r"(a));
}
__device__ __forceinline__ void ldsm4t(uint32_t* r, uint32_t a) {
    asm volatile("ldmatrix.sync.aligned.m8n8.x4.trans.shared.b16 {%0,%1,%2,%3}, [%4];"
                 : "=r"(r[0]), "=r"(r[1]), "=r"(r[2]), "=r"(r[3]) : "r"(a));
}
__device__ __forceinline__ void mma16816(float* c, const uint32_t* a, const uint32_t* b) {
    asm volatile("mma.sync.aligned.m16n8k16.row.col.f32.f16.f16.f32 "
                 "{%0,%1,%2,%3}, {%4,%5,%6,%7}, {%8,%9}, {%0,%1,%2,%3};"
                 : "+f"(c[0]), "+f"(c[1]), "+f"(c[2]), "+f"(c[3])
                 : "r"(a[0]), "r"(a[1]), "r"(a[2]), "r"(a[3]), "r"(b[0]), "r"(b[1]));
}

// Fast exp2 for t <= 0 (FMA pipe; err ~4e-5 rel)
__device__ __forceinline__ float exp2f_fast(float t) {
    t = fmaxf(t, -80.0f);
    float a = __fadd_rn(t, 12582912.0f);
    float r = __fsub_rn(t, __fsub_rn(a, 12582912.0f));
    float p = fmaf(r, 0.0096181291f, 0.0555041087f);
    p = fmaf(p, r, 0.2402265069f);
    p = fmaf(p, r, 0.6931471806f);
    p = fmaf(p, r, 1.0f);
    return __int_as_float(__float_as_int(p) + (__float_as_int(a) << 23));
}

__device__ __forceinline__ void split2(float x, float y, uint32_t& hi, uint32_t& lo) {
    __half hx = __float2half_rn(x), hy = __float2half_rn(y);
    __half2 h(hx, hy);
    hi = *reinterpret_cast<uint32_t*>(&h);
    __half2 l(__float2half_rn(x - __half2float(hx)),
              __float2half_rn(y - __half2float(hy)));
    lo = *reinterpret_cast<uint32_t*>(&l);
}
__device__ __forceinline__ uint32_t pack2(float x, float y) {
    __half2 h = __floats2half2_rn(x, y);
    return *reinterpret_cast<uint32_t*>(&h);
}

// ---------------- fused split: x -> hi/lo, Wq/Wk/Wv/Wo -> hi ----------------
#define N4X (MTOT * DMODEL / 4)        // 2097152
#define N4W (DMODEL * DMODEL / 4)      // 262144
#define SPLIT_BLOCKS ((N4X + 4 * N4W) / 256)

__global__ void split_all_kernel(const float4* __restrict__ x,
                                 const float4* __restrict__ Wq,
                                 const float4* __restrict__ Wk,
                                 const float4* __restrict__ Wv,
                                 const float4* __restrict__ Wo)
{
    int gi = blockIdx.x * 256 + threadIdx.x;
    if (gi < N4X) {
        float4 v = x[gi];
        uint32_t h0, l0, h1, l1;
        split2(v.x, v.y, h0, l0);
        split2(v.z, v.w, h1, l1);
        __half2* dh = reinterpret_cast<__half2*>(g_xh);
        __half2* dl = reinterpret_cast<__half2*>(g_xl);
        dh[2 * gi + 0] = *reinterpret_cast<__half2*>(&h0);
        dh[2 * gi + 1] = *reinterpret_cast<__half2*>(&h1);
        dl[2 * gi + 0] = *reinterpret_cast<__half2*>(&l0);
        dl[2 * gi + 1] = *reinterpret_cast<__half2*>(&l1);
    } else {
        int wi = gi - N4X;
        int z = wi / N4W;
        int i = wi - z * N4W;
        const float4* src = (z == 0) ? Wq : ((z == 1) ? Wk : ((z == 2) ? Wv : Wo));
        float4 v = src[i];
        __half2* dh = reinterpret_cast<__half2*>(g_Wh + (size_t)z * DMODEL * DMODEL);
        dh[2 * i + 0] = __half2(__float2half_rn(v.x), __float2half_rn(v.y));
        dh[2 * i + 1] = __half2(__float2half_rn(v.z), __float2half_rn(v.w));
    }
}

// ---------------- fp16 mma GEMM: C = A @ W^T + b ----------------------------
#define BM 128
#define BN 128
#define CHUNKS 16
#define ATILE 16384
#define STAGE_BYTES (3 * ATILE)
#define GEMM_SMEM   (2 * STAGE_BYTES)   // 96KB

template <int MODE>  // 0 = QKV, 1 = output proj
__global__ __launch_bounds__(256, 2) void mma_gemm(
    const float* __restrict__ b0, const float* __restrict__ b1,
    const float* __restrict__ b2, float* __restrict__ outp)
{
    extern __shared__ char smg[];
    const uint32_t sbase = smem_u32(smg);
    const int tid = threadIdx.x, wid = tid >> 5, lane = tid & 31;
    const int warp_m = wid & 3, warp_n = wid >> 2;
    const int m0 = blockIdx.x * BM;
    const int n0 = blockIdx.y * BN;
    const int z  = (MODE == 0) ? blockIdx.z : 3;
    const bool two = (MODE == 0) && (z == 0);

    const __half* Ah = (MODE == 0) ? g_xh : g_ah;
    const __half* Al = g_xl;
    const __half* Bh = g_Wh + (size_t)z * DMODEL * DMODEL;
    const float* bias = (MODE == 0) ? ((z == 0) ? b0 : ((z == 1) ? b1 : b2)) : b0;

    float cacc[2][8][4];
#pragma unroll
    for (int mi = 0; mi < 2; mi++)
#pragma unroll
        for (int ni = 0; ni < 8; ni++)
#pragma unroll
            for (int q = 0; q < 4; q++) cacc[mi][ni][q] = 0.f;

    auto load_chunk = [&](int c, int stage) {
        const int kk = c * 64;
        const uint32_t sAh = sbase + stage * STAGE_BYTES;
        const uint32_t sAl = sAh + ATILE;
        const uint32_t sB  = sAh + 2 * ATILE;
#pragma unroll
        for (int i = 0; i < 4; i++) {
            int u = tid + i * 256;       // 0..1023
            int row = u >> 3, c16 = u & 7;
            uint32_t so = swz((uint32_t)(row * 128 + c16 * 16));
            size_t go = (size_t)row * DMODEL + kk + c16 * 8;
            cp16(sAh + so, Ah + (size_t)m0 * DMODEL + go);
            if (two) cp16(sAl + so, Al + (size_t)m0 * DMODEL + go);
            cp16(sB  + so, Bh + (size_t)n0 * DMODEL + go);
        }
    };

    load_chunk(0, 0); CP_COMMIT();

    for (int c = 0; c < CHUNKS; c++) {
        CP_WAIT0();
        __syncthreads();
        if (c + 1 < CHUNKS) { load_chunk(c + 1, (c + 1) & 1); CP_COMMIT(); }

        const uint32_t sAh = sbase + (c & 1) * STAGE_BYTES;
        const uint32_t sAl = sAh + ATILE;
        const uint32_t sB  = sAh + 2 * ATILE;

#pragma unroll
        for (int ks = 0; ks < 4; ks++) {
            uint32_t ah[2][4], al[2][4], b[4][4];
#pragma unroll
            for (int mi = 0; mi < 2; mi++) {
                int r = warp_m * 32 + mi * 16 + (lane & 15);
                uint32_t so = swz((uint32_t)(r * 128 + ks * 32 + ((lane >> 4) << 4)));
                ldsm4(ah[mi], sAh + so);
                if (two) ldsm4(al[mi], sAl + so);
            }
#pragma unroll
            for (int nb = 0; nb < 4; nb++) {
                int n = warp_n * 64 + nb * 16 + (lane & 7) + ((lane >> 4) << 3);
                ldsm4(b[nb], sB + swz((uint32_t)(n * 128 + ks * 32 + (((lane >> 3) & 1) << 4))));
            }
#pragma unroll
            for (int mi = 0; mi < 2; mi++)
#pragma unroll
                for (int ni = 0; ni < 8; ni++) {
                    mma16816(cacc[mi][ni], ah[mi], &b[ni >> 1][(ni & 1) * 2]);
                    if (two) mma16816(cacc[mi][ni], al[mi], &b[ni >> 1][(ni & 1) * 2]);
                }
        }
    }

    const int row_base = m0 + warp_m * 32 + (lane >> 2);
    const int col_base = n0 + warp_n * 64 + (lane & 3) * 2;
#pragma unroll
    for (int ni = 0; ni < 8; ni++) {
        const int cc = col_base + ni * 8;
        const float bz0 = __ldg(&bias[cc]);
        const float bz1 = __ldg(&bias[cc + 1]);
#pragma unroll
        for (int mi = 0; mi < 2; mi++) {
#pragma unroll
            for (int half = 0; half < 2; half++) {
                const int m = row_base + mi * 16 + half * 8;
                float vx = cacc[mi][ni][half * 2 + 0] + bz0;
                float vy = cacc[mi][ni][half * 2 + 1] + bz1;
                if (MODE == 0) {
                    const int bb = m >> 11, s = m & (SEQ - 1);
                    const int hd = cc >> 6, d = cc & 63;
                    size_t idx = (((size_t)(bb * NHEADS + hd)) * SEQ + s) * DK + d;
                    if (z == 0) {
                        vx *= QSCALE; vy *= QSCALE;
                        __half hx = __float2half_rn(vx), hy = __float2half_rn(vy);
                        *reinterpret_cast<__half2*>(g_Qh + idx) = __half2(hx, hy);
                        *reinterpret_cast<__half2*>(g_Ql + idx) =
                            __half2(__float2half_rn(vx - __half2float(hx)),
                                    __float2half_rn(vy - __half2float(hy)));
                    } else if (z == 1) {
                        *reinterpret_cast<__half2*>(g_Kh + idx) =
                            __half2(__float2half_rn(vx), __float2half_rn(vy));
                    } else {
                        *reinterpret_cast<__half2*>(g_Vh + idx) =
                            __half2(__float2half_rn(vx), __float2half_rn(vy));
                    }
                } else {
                    float2 v; v.x = vx; v.y = vy;
                    *reinterpret_cast<float2*>(&outp[(size_t)m * DMODEL + cc]) = v;
                }
            }
        }
    }
}

// ---------------- tensor-core causal flash attention (fp16) -----------------
// Q tile 128 (Qh+Ql, 32KB parked), KV tile 128 keys (K 16KB + V 16KB = 32KB
// per stage), 3 stages. 128KB smem, 1 CTA/SM. Half the iterations of R9.
#define ASTAGE_BYTES 32768
#define AQ_OFF       (3 * ASTAGE_BYTES)
#define ATTN_SMEM    (3 * ASTAGE_BYTES + 32768)   // 128KB

__global__ __launch_bounds__(256, 1) void attn_mma_kernel()
{
    extern __shared__ char smem[];
    const uint32_t sb = smem_u32(smem);
    const int tid = threadIdx.x, wid = tid >> 5, lane = tid & 31;
    const int qi = gridDim.x - 1 - blockIdx.x;   // long tiles first
    const int bh = blockIdx.y;
    const int q0 = qi * 128;
    const size_t base = (size_t)bh * SEQ * DK;

    const int nkt = qi + 1;                      // 128-key tiles, causal
    auto load_kv = [&](int kt) {
        uint32_t st = sb + (uint32_t)(kt % 3) * ASTAGE_BYTES;
        const size_t ko = base + (size_t)kt * 128 * DK;
#pragma unroll
        for (int i = 0; i < 4; i++) {
            int u = tid + i * 256;        // 0..1023
            int row = u >> 3, c16 = u & 7;
            uint32_t so = swz((uint32_t)(row * 128 + c16 * 16));
            cp16(st + so,         g_Kh + ko + (size_t)row * DK + c16 * 8);
            cp16(st + 16384 + so, g_Vh + ko + (size_t)row * DK + c16 * 8);
        }
    };

    // group0: Q + kv0
    const uint32_t sQh = sb + AQ_OFF;
    const uint32_t sQl = sb + AQ_OFF + 16384;
#pragma unroll
    for (int i = 0; i < 4; i++) {
        int u = tid + i * 256;
        int row = u >> 3, c16 = u & 7;
        uint32_t so = swz((uint32_t)(row * 128 + c16 * 16));
        cp16(sQh + so, g_Qh + base + (size_t)(q0 + row) * DK + c16 * 8);
        cp16(sQl + so, g_Ql + base + (size_t)(q0 + row) * DK + c16 * 8);
    }
    load_kv(0);
    CP_COMMIT();
    if (nkt > 1) { load_kv(1); CP_COMMIT(); }

    // wait group0 (Q + kv0)
    if (nkt > 1) CP_WAIT1(); else CP_WAIT0();
    __syncthreads();

    uint32_t qh[4][4], ql[4][4];
    {
        int r = wid * 16 + (lane & 15);
        uint32_t half = (uint32_t)((lane >> 4) << 4);
#pragma unroll
        for (int kc = 0; kc < 4; kc++) {
            ldsm4(qh[kc], sQh + swz((uint32_t)(r * 128 + kc * 32) + half));
            ldsm4(ql[kc], sQl + swz((uint32_t)(r * 128 + kc * 32) + half));
        }
    }

    const int nrow = (lane & 7) + ((lane >> 4) << 3);
    const uint32_t koff = (uint32_t)(((lane >> 3) & 1) << 4);
    const int vkey = ((lane >> 3) & 1) * 8 + (lane & 7);
    const uint32_t vdk = (uint32_t)(((lane >> 4) << 3) * 2);

    float o[8][4];
#pragma unroll
    for (int nt = 0; nt < 8; nt++)
#pragma unroll
        for (int q = 0; q < 4; q++) o[nt][q] = 0.f;
    float m0v = -3.0e38f, m1v = -3.0e38f, l0 = 0.f, l1 = 0.f;

    const int rq = q0 + wid * 16 + (lane >> 2);

    for (int kt = 0; kt < nkt; kt++) {
        if (kt > 0) {
            const int rem = nkt - 1 - kt;        // groups newer than kv(kt)
            if (rem >= 2) CP_WAIT2();
            else if (rem == 1) CP_WAIT1();
            else CP_WAIT0();
            __syncthreads();
        }
        if (kt + 2 < nkt) { load_kv(kt + 2); CP_COMMIT(); }

        const uint32_t st = sb + (uint32_t)(kt % 3) * ASTAGE_BYTES;

        // ---- S[128q x 128k] = (Qh+Ql)·Kh ----
        float s[16][4];
#pragma unroll
        for (int nt = 0; nt < 16; nt++)
#pragma unroll
            for (int q = 0; q < 4; q++) s[nt][q] = 0.f;

#pragma unroll
        for (int kc = 0; kc < 4; kc++) {
            uint32_t kb[32];
#pragma unroll
            for (int nb = 0; nb < 8; nb++)
                ldsm4(kb + nb * 4, st + swz((uint32_t)((nb * 16 + nrow) * 128 + kc * 32) + koff));
#pragma unroll
            for (int nt = 0; nt < 16; nt++) mma16816(s[nt], qh[kc], &kb[nt * 2]);
#pragma unroll
            for (int nt = 0; nt < 16; nt++) mma16816(s[nt], ql[kc], &kb[nt * 2]);
        }

        // ---- causal mask (only the diagonal tile kt == qi) ----
        if (kt == qi) {
            const int cb = kt * 128 + 2 * (lane & 3);
#pragma unroll
            for (int nt = 0; nt < 16; nt++) {
                int c0 = cb + 8 * nt;
                if (c0     > rq)     s[nt][0] = -1.0e30f;
                if (c0 + 1 > rq)     s[nt][1] = -1.0e30f;
                if (c0     > rq + 8) s[nt][2] = -1.0e30f;
                if (c0 + 1 > rq + 8) s[nt][3] = -1.0e30f;
            }
        }

        // ---- online softmax over 128 cols ----
        float mx0 = -3.0e38f, mx1 = -3.0e38f;
#pragma unroll
        for (int nt = 0; nt < 16; nt++) {
            mx0 = fmaxf(mx0, fmaxf(s[nt][0], s[nt][1]));
            mx1 = fmaxf(mx1, fmaxf(s[nt][2], s[nt][3]));
        }
        mx0 = fmaxf(mx0, __shfl_xor_sync(0xFFFFFFFFu, mx0, 1));
        mx0 = fmaxf(mx0, __shfl_xor_sync(0xFFFFFFFFu, mx0, 2));
        mx1 = fmaxf(mx1, __shfl_xor_sync(0xFFFFFFFFu, mx1, 1));
        mx1 = fmaxf(mx1, __shfl_xor_sync(0xFFFFFFFFu, mx1, 2));
        const float mn0 = fmaxf(m0v, mx0), mn1 = fmaxf(m1v, mx1);
        const float f0 = exp2f_fast(m0v - mn0), f1 = exp2f_fast(m1v - mn1);
        m0v = mn0; m1v = mn1;

        float sum0 = 0.f, sum1 = 0.f;
        uint32_t ph[8][4];
#pragma unroll
        for (int kc = 0; kc < 8; kc++) {
            float e00 = exp2f_fast(s[2*kc][0]   - mn0);
            float e01 = exp2f_fast(s[2*kc][1]   - mn0);
            float e10 = exp2f_fast(s[2*kc][2]   - mn1);
            float e11 = exp2f_fast(s[2*kc][3]   - mn1);
            float e20 = exp2f_fast(s[2*kc+1][0] - mn0);
            float e21 = exp2f_fast(s[2*kc+1][1] - mn0);
            float e30 = exp2f_fast(s[2*kc+1][2] - mn1);
            float e31 = exp2f_fast(s[2*kc+1][3] - mn1);
            sum0 += (e00 + e01) + (e20 + e21);
            sum1 += (e10 + e11) + (e30 + e31);
            ph[kc][0] = pack2(e00, e01);
            ph[kc][1] = pack2(e10, e11);
            ph[kc][2] = pack2(e20, e21);
            ph[kc][3] = pack2(e30, e31);
        }
        sum0 += __shfl_xor_sync(0xFFFFFFFFu, sum0, 1);
        sum0 += __shfl_xor_sync(0xFFFFFFFFu, sum0, 2);
        sum1 += __shfl_xor_sync(0xFFFFFFFFu, sum1, 1);
        sum1 += __shfl_xor_sync(0xFFFFFFFFu, sum1, 2);
        l0 = l0 * f0 + sum0;
        l1 = l1 * f1 + sum1;

#pragma unroll
        for (int nt = 0; nt < 8; nt++) {
            o[nt][0] *= f0; o[nt][1] *= f0;
            o[nt][2] *= f1; o[nt][3] *= f1;
        }

        // ---- O += Ph·Vh over 128 keys ----
        const uint32_t stv = st + 16384;
#pragma unroll
        for (int kc = 0; kc < 8; kc++) {
            uint32_t vb[16];
#pragma unroll
            for (int p4 = 0; p4 < 4; p4++)
                ldsm4t(vb + p4 * 4, stv +
                       swz((uint32_t)((kc * 16 + vkey) * 128 + p4 * 32) + vdk));
#pragma unroll
            for (int nt = 0; nt < 8; nt++) mma16816(o[nt], ph[kc], &vb[nt * 2]);
        }
    }

    // ---- epilogue: normalize, store fp16 hi to [B,S,H*DK] ----
    const float inv0 = 1.0f / l0, inv1 = 1.0f / l1;
    const int b = bh >> 4, hd = bh & 15;
    const int dkb = 2 * (lane & 3);
#pragma unroll
    for (int nt = 0; nt < 8; nt++) {
        const int d = hd * 64 + dkb + 8 * nt;
        size_t i0 = ((size_t)b * SEQ + rq) * DMODEL + d;
        size_t i1 = ((size_t)b * SEQ + rq + 8) * DMODEL + d;
        uint32_t p0 = pack2(o[nt][0] * inv0, o[nt][1] * inv0);
        uint32_t p1 = pack2(o[nt][2] * inv1, o[nt][3] * inv1);
        *reinterpret_cast<uint32_t*>(g_ah + i0) = p0;
        *reinterpret_cast<uint32_t*>(g_ah + i1) = p1;
    }
}

// ---------------------------------------------------------------------------
extern "C" void kernel_launch(void* const* d_in, const int* in_sizes, int n_in,
                              void* d_out, int out_size)
{
    const float* x  = (const float*)d_in[0];
    const float* Wq = (const float*)d_in[1];
    const float* bq = (const float*)d_in[2];
    const float* Wk = (const float*)d_in[3];
    const float* bk = (const float*)d_in[4];
    const float* Wv = (const float*)d_in[5];
    const float* bv = (const float*)d_in[6];
    const float* Wo = (const float*)d_in[7];
    const float* bo = (const float*)d_in[8];
    float* out = (float*)d_out;
    (void)in_sizes; (void)n_in; (void)out_size;

    static bool attr_done = false;
    if (!attr_done) {
        cudaFuncSetAttribute(mma_gemm<0>, cudaFuncAttributeMaxDynamicSharedMemorySize, GEMM_SMEM);
        cudaFuncSetAttribute(mma_gemm<1>, cudaFuncAttributeMaxDynamicSharedMemorySize, GEMM_SMEM);
        cudaFuncSetAttribute(attn_mma_kernel, cudaFuncAttributeMaxDynamicSharedMemorySize, ATTN_SMEM);
        attr_done = true;
    }

    split_all_kernel<<<SPLIT_BLOCKS, 256>>>((const float4*)x, (const float4*)Wq,
                                            (const float4*)Wk, (const float4*)Wv,
                                            (const float4*)Wo);

    dim3 gQKV(MTOT / BM, DMODEL / BN, 3);
    mma_gemm<0><<<gQKV, 256, GEMM_SMEM>>>(bq, bk, bv, nullptr);

    dim3 gAttn(SEQ / 128, BATCH * NHEADS);
    attn_mma_kernel<<<gAttn, 256, ATTN_SMEM>>>();

    dim3 gProj(MTOT / BM, DMODEL / BN);
    mma_gemm<1><<<gProj, 256, GEMM_SMEM>>>(bo, nullptr, nullptr, out);
}

// round 11
// speedup vs baseline: 1.0818x; 1.0818x over previous
#include <cuda_runtime.h>
#include <cuda_fp16.h>
#include <cstdint>
#include <math.h>

#define DMODEL 1024
#define NHEADS 16
#define DK     64
#define BATCH  4
#define SEQ    2048
#define MTOT   (BATCH*SEQ)   // 8192

#define QSCALE 0.1803368801111204f   // 0.125 * log2(e)

// ---------------- device scratch (allocation-free) ----------------
__device__ __half g_Qh[(size_t)MTOT * DMODEL];  // [B*H][S][DK]
__device__ __half g_Ql[(size_t)MTOT * DMODEL];
__device__ __half g_Kh[(size_t)MTOT * DMODEL];  // hi only
__device__ __half g_Vh[(size_t)MTOT * DMODEL];  // hi only
__device__ __half g_xh[(size_t)MTOT * DMODEL];
__device__ __half g_xl[(size_t)MTOT * DMODEL];
__device__ __half g_Wh[(size_t)4 * DMODEL * DMODEL];   // weights hi only
__device__ __half g_ah[(size_t)MTOT * DMODEL];  // attn out (hi only) [B,S,H*DK]

// ---------------- helpers ----------------
__device__ __forceinline__ uint32_t smem_u32(const void* p) {
    uint32_t a;
    asm("{ .reg .u64 t; cvta.to.shared.u64 t, %1; cvt.u32.u64 %0, t; }" : "=r"(a) : "l"(p));
    return a;
}
__device__ __forceinline__ uint32_t swz(uint32_t o) { return o ^ ((o >> 3) & 0x70); }

__device__ __forceinline__ void cp16(uint32_t dst, const void* src) {
    asm volatile("cp.async.cg.shared.global [%0], [%1], 16;" :: "r"(dst), "l"(src));
}
#define CP_COMMIT() asm volatile("cp.async.commit_group;" ::: "memory")
#define CP_WAIT0()  asm volatile("cp.async.wait_group 0;" ::: "memory")
#define CP_WAIT1()  asm volatile("cp.async.wait_group 1;" ::: "memory")
#define CP_WAIT2()  asm volatile("cp.async.wait_group 2;" ::: "memory")

__device__ __forceinline__ void ldsm4(uint32_t* r, uint32_t a) {
    asm volatile("ldmatrix.sync.aligned.m8n8.x4.shared.b16 {%0,%1,%2,%3}, [%4];"
                 : "=r"(r[0]), "=r"(r[1]), "=r"(r[2]), "=r"(r[3]) : "r"(a));
}
__device__ __forceinline__ void ldsm4t(uint32_t* r, uint32_t a) {
    asm volatile("ldmatrix.sync.aligned.m8n8.x4.trans.shared.b16 {%0,%1,%2,%3}, [%4];"
                 : "=r"(r[0]), "=r"(r[1]), "=r"(r[2]), "=r"(r[3]) : "r"(a));
}
__device__ __forceinline__ void mma16816(float* c, const uint32_t* a, const uint32_t* b) {
    asm volatile("mma.sync.aligned.m16n8k16.row.col.f32.f16.f16.f32 "
                 "{%0,%1,%2,%3}, {%4,%5,%6,%7}, {%8,%9}, {%0,%1,%2,%3};"
                 : "+f"(c[0]), "+f"(c[1]), "+f"(c[2]), "+f"(c[3])
                 : "r"(a[0]), "r"(a[1]), "r"(a[2]), "r"(a[3]), "r"(b[0]), "r"(b[1]));
}

// Fast exp2 for t <= 0 (FMA pipe; err ~4e-5 rel)
__device__ __forceinline__ float exp2f_fast(float t) {
    t = fmaxf(t, -80.0f);
    float a = __fadd_rn(t, 12582912.0f);
    float r = __fsub_rn(t, __fsub_rn(a, 12582912.0f));
    float p = fmaf(r, 0.0096181291f, 0.0555041087f);
    p = fmaf(p, r, 0.2402265069f);
    p = fmaf(p, r, 0.6931471806f);
    p = fmaf(p, r, 1.0f);
    return __int_as_float(__float_as_int(p) + (__float_as_int(a) << 23));
}

__device__ __forceinline__ void split2(float x, float y, uint32_t& hi, uint32_t& lo) {
    __half hx = __float2half_rn(x), hy = __float2half_rn(y);
    __half2 h(hx, hy);
    hi = *reinterpret_cast<uint32_t*>(&h);
    __half2 l(__float2half_rn(x - __half2float(hx)),
              __float2half_rn(y - __half2float(hy)));
    lo = *reinterpret_cast<uint32_t*>(&l);
}
__device__ __forceinline__ uint32_t pack2(float x, float y) {
    __half2 h = __floats2half2_rn(x, y);
    return *reinterpret_cast<uint32_t*>(&h);
}

// ---------------- fused split: x -> hi/lo, Wq/Wk/Wv/Wo -> hi ----------------
#define N4X (MTOT * DMODEL / 4)        // 2097152
#define N4W (DMODEL * DMODEL / 4)      // 262144
#define SPLIT_BLOCKS ((N4X + 4 * N4W) / 256)

__global__ void split_all_kernel(const float4* __restrict__ x,
                                 const float4* __restrict__ Wq,
                                 const float4* __restrict__ Wk,
                                 const float4* __restrict__ Wv,
                                 const float4* __restrict__ Wo)
{
    int gi = blockIdx.x * 256 + threadIdx.x;
    if (gi < N4X) {
        float4 v = x[gi];
        uint32_t h0, l0, h1, l1;
        split2(v.x, v.y, h0, l0);
        split2(v.z, v.w, h1, l1);
        __half2* dh = reinterpret_cast<__half2*>(g_xh);
        __half2* dl = reinterpret_cast<__half2*>(g_xl);
        dh[2 * gi + 0] = *reinterpret_cast<__half2*>(&h0);
        dh[2 * gi + 1] = *reinterpret_cast<__half2*>(&h1);
        dl[2 * gi + 0] = *reinterpret_cast<__half2*>(&l0);
        dl[2 * gi + 1] = *reinterpret_cast<__half2*>(&l1);
    } else {
        int wi = gi - N4X;
        int z = wi / N4W;
        int i = wi - z * N4W;
        const float4* src = (z == 0) ? Wq : ((z == 1) ? Wk : ((z == 2) ? Wv : Wo));
        float4 v = src[i];
        __half2* dh = reinterpret_cast<__half2*>(g_Wh + (size_t)z * DMODEL * DMODEL);
        dh[2 * i + 0] = __half2(__float2half_rn(v.x), __float2half_rn(v.y));
        dh[2 * i + 1] = __half2(__float2half_rn(v.z), __float2half_rn(v.w));
    }
}

// ---------------- fp16 mma GEMM: C = A @ W^T + b ----------------------------
#define BM 128
#define BN 128
#define CHUNKS 16
#define ATILE 16384
#define STAGE_BYTES (3 * ATILE)
#define GEMM_SMEM   (2 * STAGE_BYTES)   // 96KB

template <int MODE>  // 0 = QKV, 1 = output proj
__global__ __launch_bounds__(256, 2) void mma_gemm(
    const float* __restrict__ b0, const float* __restrict__ b1,
    const float* __restrict__ b2, float* __restrict__ outp)
{
    extern __shared__ char smg[];
    const uint32_t sbase = smem_u32(smg);
    const int tid = threadIdx.x, wid = tid >> 5, lane = tid & 31;
    const int warp_m = wid & 3, warp_n = wid >> 2;
    const int m0 = blockIdx.x * BM;
    const int n0 = blockIdx.y * BN;
    const int z  = (MODE == 0) ? blockIdx.z : 3;
    const bool two = (MODE == 0) && (z == 0);

    const __half* Ah = (MODE == 0) ? g_xh : g_ah;
    const __half* Al = g_xl;
    const __half* Bh = g_Wh + (size_t)z * DMODEL * DMODEL;
    const float* bias = (MODE == 0) ? ((z == 0) ? b0 : ((z == 1) ? b1 : b2)) : b0;

    float cacc[2][8][4];
#pragma unroll
    for (int mi = 0; mi < 2; mi++)
#pragma unroll
        for (int ni = 0; ni < 8; ni++)
#pragma unroll
            for (int q = 0; q < 4; q++) cacc[mi][ni][q] = 0.f;

    auto load_chunk = [&](int c, int stage) {
        const int kk = c * 64;
        const uint32_t sAh = sbase + stage * STAGE_BYTES;
        const uint32_t sAl = sAh + ATILE;
        const uint32_t sB  = sAh + 2 * ATILE;
#pragma unroll
        for (int i = 0; i < 4; i++) {
            int u = tid + i * 256;       // 0..1023
            int row = u >> 3, c16 = u & 7;
            uint32_t so = swz((uint32_t)(row * 128 + c16 * 16));
            size_t go = (size_t)row * DMODEL + kk + c16 * 8;
            cp16(sAh + so, Ah + (size_t)m0 * DMODEL + go);
            if (two) cp16(sAl + so, Al + (size_t)m0 * DMODEL + go);
            cp16(sB  + so, Bh + (size_t)n0 * DMODEL + go);
        }
    };

    load_chunk(0, 0); CP_COMMIT();

    for (int c = 0; c < CHUNKS; c++) {
        CP_WAIT0();
        __syncthreads();
        if (c + 1 < CHUNKS) { load_chunk(c + 1, (c + 1) & 1); CP_COMMIT(); }

        const uint32_t sAh = sbase + (c & 1) * STAGE_BYTES;
        const uint32_t sAl = sAh + ATILE;
        const uint32_t sB  = sAh + 2 * ATILE;

#pragma unroll
        for (int ks = 0; ks < 4; ks++) {
            uint32_t ah[2][4], al[2][4], b[4][4];
#pragma unroll
            for (int mi = 0; mi < 2; mi++) {
                int r = warp_m * 32 + mi * 16 + (lane & 15);
                uint32_t so = swz((uint32_t)(r * 128 + ks * 32 + ((lane >> 4) << 4)));
                ldsm4(ah[mi], sAh + so);
                if (two) ldsm4(al[mi], sAl + so);
            }
#pragma unroll
            for (int nb = 0; nb < 4; nb++) {
                int n = warp_n * 64 + nb * 16 + (lane & 7) + ((lane >> 4) << 3);
                ldsm4(b[nb], sB + swz((uint32_t)(n * 128 + ks * 32 + (((lane >> 3) & 1) << 4))));
            }
#pragma unroll
            for (int mi = 0; mi < 2; mi++)
#pragma unroll
                for (int ni = 0; ni < 8; ni++) {
                    mma16816(cacc[mi][ni], ah[mi], &b[ni >> 1][(ni & 1) * 2]);
                    if (two) mma16816(cacc[mi][ni], al[mi], &b[ni >> 1][(ni & 1) * 2]);
                }
        }
    }

    const int row_base = m0 + warp_m * 32 + (lane >> 2);
    const int col_base = n0 + warp_n * 64 + (lane & 3) * 2;
#pragma unroll
    for (int ni = 0; ni < 8; ni++) {
        const int cc = col_base + ni * 8;
        const float bz0 = __ldg(&bias[cc]);
        const float bz1 = __ldg(&bias[cc + 1]);
#pragma unroll
        for (int mi = 0; mi < 2; mi++) {
#pragma unroll
            for (int half = 0; half < 2; half++) {
                const int m = row_base + mi * 16 + half * 8;
                float vx = cacc[mi][ni][half * 2 + 0] + bz0;
                float vy = cacc[mi][ni][half * 2 + 1] + bz1;
                if (MODE == 0) {
                    const int bb = m >> 11, s = m & (SEQ - 1);
                    const int hd = cc >> 6, d = cc & 63;
                    size_t idx = (((size_t)(bb * NHEADS + hd)) * SEQ + s) * DK + d;
                    if (z == 0) {
                        vx *= QSCALE; vy *= QSCALE;
                        __half hx = __float2half_rn(vx), hy = __float2half_rn(vy);
                        *reinterpret_cast<__half2*>(g_Qh + idx) = __half2(hx, hy);
                        *reinterpret_cast<__half2*>(g_Ql + idx) =
                            __half2(__float2half_rn(vx - __half2float(hx)),
                                    __float2half_rn(vy - __half2float(hy)));
                    } else if (z == 1) {
                        *reinterpret_cast<__half2*>(g_Kh + idx) =
                            __half2(__float2half_rn(vx), __float2half_rn(vy));
                    } else {
                        *reinterpret_cast<__half2*>(g_Vh + idx) =
                            __half2(__float2half_rn(vx), __float2half_rn(vy));
                    }
                } else {
                    float2 v; v.x = vx; v.y = vy;
                    *reinterpret_cast<float2*>(&outp[(size_t)m * DMODEL + cc]) = v;
                }
            }
        }
    }
}

// ---------------- tensor-core causal flash attention (fp16) -----------------
// 128 threads / 4 warps per CTA, Q tile 64 rows (warp = 16 rows), KV tile 64,
// 3 KV stages of 16KB + Q 16KB = 64KB smem -> 3 CTAs/SM, no register spills.
#define ASTAGE_BYTES 16384
#define AQ_OFF       (3 * ASTAGE_BYTES)
#define ATTN_SMEM    (AQ_OFF + 16384)   // 64KB

__global__ __launch_bounds__(128, 3) void attn_mma_kernel()
{
    extern __shared__ char smem[];
    const uint32_t sb = smem_u32(smem);
    const int tid = threadIdx.x, wid = tid >> 5, lane = tid & 31;
    const int qi = gridDim.x - 1 - blockIdx.x;   // long tiles first
    const int bh = blockIdx.y;
    const int q0 = qi * 64;
    const size_t base = (size_t)bh * SEQ * DK;

    const int nkt = qi + 1;
    auto load_kv = [&](int kt) {
        uint32_t st = sb + (uint32_t)(kt % 3) * ASTAGE_BYTES;
        const size_t ko = base + (size_t)kt * 64 * DK;
#pragma unroll
        for (int i = 0; i < 4; i++) {
            int u = tid + i * 128;        // 0..511
            int row = u >> 3, c16 = u & 7;
            uint32_t so = swz((uint32_t)(row * 128 + c16 * 16));
            cp16(st + so,        g_Kh + ko + (size_t)row * DK + c16 * 8);
            cp16(st + 8192 + so, g_Vh + ko + (size_t)row * DK + c16 * 8);
        }
    };

    // group0: Q (Qh 8KB + Ql 8KB) + kv0
    const uint32_t sQh = sb + AQ_OFF;
    const uint32_t sQl = sb + AQ_OFF + 8192;
#pragma unroll
    for (int i = 0; i < 4; i++) {
        int u = tid + i * 128;            // 0..511
        int row = u >> 3, c16 = u & 7;
        uint32_t so = swz((uint32_t)(row * 128 + c16 * 16));
        cp16(sQh + so, g_Qh + base + (size_t)(q0 + row) * DK + c16 * 8);
        cp16(sQl + so, g_Ql + base + (size_t)(q0 + row) * DK + c16 * 8);
    }
    load_kv(0);
    CP_COMMIT();
    if (nkt > 1) { load_kv(1); CP_COMMIT(); }

    if (nkt > 1) CP_WAIT1(); else CP_WAIT0();
    __syncthreads();

    uint32_t qh[4][4], ql[4][4];
    {
        int r = wid * 16 + (lane & 15);
        uint32_t half = (uint32_t)((lane >> 4) << 4);
#pragma unroll
        for (int kc = 0; kc < 4; kc++) {
            ldsm4(qh[kc], sQh + swz((uint32_t)(r * 128 + kc * 32) + half));
            ldsm4(ql[kc], sQl + swz((uint32_t)(r * 128 + kc * 32) + half));
        }
    }

    const int nrow = (lane & 7) + ((lane >> 4) << 3);
    const uint32_t koff = (uint32_t)(((lane >> 3) & 1) << 4);
    const int vkey = ((lane >> 3) & 1) * 8 + (lane & 7);
    const uint32_t vdk = (uint32_t)(((lane >> 4) << 3) * 2);

    float o[8][4];
#pragma unroll
    for (int nt = 0; nt < 8; nt++)
#pragma unroll
        for (int q = 0; q < 4; q++) o[nt][q] = 0.f;
    float m0v = -3.0e38f, m1v = -3.0e38f, l0 = 0.f, l1 = 0.f;

    const int rq = q0 + wid * 16 + (lane >> 2);

    for (int kt = 0; kt < nkt; kt++) {
        if (kt > 0) {
            const int rem = nkt - 1 - kt;        // groups newer than kv(kt)
            if (rem >= 2) CP_WAIT2();
            else if (rem == 1) CP_WAIT1();
            else CP_WAIT0();
            __syncthreads();
        }
        if (kt + 2 < nkt) { load_kv(kt + 2); CP_COMMIT(); }

        const uint32_t st = sb + (uint32_t)(kt % 3) * ASTAGE_BYTES;

        // ---- S[64q x 64k] = (Qh+Ql)·Kh ----
        float s[8][4];
#pragma unroll
        for (int nt = 0; nt < 8; nt++)
#pragma unroll
            for (int q = 0; q < 4; q++) s[nt][q] = 0.f;

#pragma unroll
        for (int kc = 0; kc < 4; kc++) {
            uint32_t kb[16];
#pragma unroll
            for (int nb = 0; nb < 4; nb++)
                ldsm4(kb + nb * 4, st + swz((uint32_t)((nb * 16 + nrow) * 128 + kc * 32) + koff));
#pragma unroll
            for (int nt = 0; nt < 8; nt++) mma16816(s[nt], qh[kc], &kb[nt * 2]);
#pragma unroll
            for (int nt = 0; nt < 8; nt++) mma16816(s[nt], ql[kc], &kb[nt * 2]);
        }

        // ---- causal mask (diagonal tile only) ----
        if (kt == qi) {
            const int cb = kt * 64 + 2 * (lane & 3);
#pragma unroll
            for (int nt = 0; nt < 8; nt++) {
                int c0 = cb + 8 * nt;
                if (c0     > rq)     s[nt][0] = -1.0e30f;
                if (c0 + 1 > rq)     s[nt][1] = -1.0e30f;
                if (c0     > rq + 8) s[nt][2] = -1.0e30f;
                if (c0 + 1 > rq + 8) s[nt][3] = -1.0e30f;
            }
        }

        // ---- online softmax ----
        float mx0 = -3.0e38f, mx1 = -3.0e38f;
#pragma unroll
        for (int nt = 0; nt < 8; nt++) {
            mx0 = fmaxf(mx0, fmaxf(s[nt][0], s[nt][1]));
            mx1 = fmaxf(mx1, fmaxf(s[nt][2], s[nt][3]));
        }
        mx0 = fmaxf(mx0, __shfl_xor_sync(0xFFFFFFFFu, mx0, 1));
        mx0 = fmaxf(mx0, __shfl_xor_sync(0xFFFFFFFFu, mx0, 2));
        mx1 = fmaxf(mx1, __shfl_xor_sync(0xFFFFFFFFu, mx1, 1));
        mx1 = fmaxf(mx1, __shfl_xor_sync(0xFFFFFFFFu, mx1, 2));
        const float mn0 = fmaxf(m0v, mx0), mn1 = fmaxf(m1v, mx1);
        const float f0 = exp2f_fast(m0v - mn0), f1 = exp2f_fast(m1v - mn1);
        m0v = mn0; m1v = mn1;

        float sum0 = 0.f, sum1 = 0.f;
        uint32_t ph[4][4];
#pragma unroll
        for (int kc = 0; kc < 4; kc++) {
            float e00 = exp2f_fast(s[2*kc][0]   - mn0);
            float e01 = exp2f_fast(s[2*kc][1]   - mn0);
            float e10 = exp2f_fast(s[2*kc][2]   - mn1);
            float e11 = exp2f_fast(s[2*kc][3]   - mn1);
            float e20 = exp2f_fast(s[2*kc+1][0] - mn0);
            float e21 = exp2f_fast(s[2*kc+1][1] - mn0);
            float e30 = exp2f_fast(s[2*kc+1][2] - mn1);
            float e31 = exp2f_fast(s[2*kc+1][3] - mn1);
            sum0 += (e00 + e01) + (e20 + e21);
            sum1 += (e10 + e11) + (e30 + e31);
            ph[kc][0] = pack2(e00, e01);
            ph[kc][1] = pack2(e10, e11);
            ph[kc][2] = pack2(e20, e21);
            ph[kc][3] = pack2(e30, e31);
        }
        sum0 += __shfl_xor_sync(0xFFFFFFFFu, sum0, 1);
        sum0 += __shfl_xor_sync(0xFFFFFFFFu, sum0, 2);
        sum1 += __shfl_xor_sync(0xFFFFFFFFu, sum1, 1);
        sum1 += __shfl_xor_sync(0xFFFFFFFFu, sum1, 2);
        l0 = l0 * f0 + sum0;
        l1 = l1 * f1 + sum1;

#pragma unroll
        for (int nt = 0; nt < 8; nt++) {
            o[nt][0] *= f0; o[nt][1] *= f0;
            o[nt][2] *= f1; o[nt][3] *= f1;
        }

        // ---- O += Ph·Vh ----
        const uint32_t stv = st + 8192;
#pragma unroll
        for (int kc = 0; kc < 4; kc++) {
            uint32_t vb[16];
#pragma unroll
            for (int p4 = 0; p4 < 4; p4++)
                ldsm4t(vb + p4 * 4, stv +
                       swz((uint32_t)((kc * 16 + vkey) * 128 + p4 * 32) + vdk));
#pragma unroll
            for (int nt = 0; nt < 8; nt++) mma16816(o[nt], ph[kc], &vb[nt * 2]);
        }
    }

    // ---- epilogue: normalize, store fp16 hi to [B,S,H*DK] ----
    const float inv0 = 1.0f / l0, inv1 = 1.0f / l1;
    const int b = bh >> 4, hd = bh & 15;
    const int dkb = 2 * (lane & 3);
#pragma unroll
    for (int nt = 0; nt < 8; nt++) {
        const int d = hd * 64 + dkb + 8 * nt;
        size_t i0 = ((size_t)b * SEQ + rq) * DMODEL + d;
        size_t i1 = ((size_t)b * SEQ + rq + 8) * DMODEL + d;
        uint32_t p0 = pack2(o[nt][0] * inv0, o[nt][1] * inv0);
        uint32_t p1 = pack2(o[nt][2] * inv1, o[nt][3] * inv1);
        *reinterpret_cast<uint32_t*>(g_ah + i0) = p0;
        *reinterpret_cast<uint32_t*>(g_ah + i1) = p1;
    }
}

// ---------------------------------------------------------------------------
extern "C" void kernel_launch(void* const* d_in, const int* in_sizes, int n_in,
                              void* d_out, int out_size)
{
    const float* x  = (const float*)d_in[0];
    const float* Wq = (const float*)d_in[1];
    const float* bq = (const float*)d_in[2];
    const float* Wk = (const float*)d_in[3];
    const float* bk = (const float*)d_in[4];
    const float* Wv = (const float*)d_in[5];
    const float* bv = (const float*)d_in[6];
    const float* Wo = (const float*)d_in[7];
    const float* bo = (const float*)d_in[8];
    float* out = (float*)d_out;
    (void)in_sizes; (void)n_in; (void)out_size;

    static bool attr_done = false;
    if (!attr_done) {
        cudaFuncSetAttribute(mma_gemm<0>, cudaFuncAttributeMaxDynamicSharedMemorySize, GEMM_SMEM);
        cudaFuncSetAttribute(mma_gemm<1>, cudaFuncAttributeMaxDynamicSharedMemorySize, GEMM_SMEM);
        cudaFuncSetAttribute(attn_mma_kernel, cudaFuncAttributeMaxDynamicSharedMemorySize, ATTN_SMEM);
        attr_done = true;
    }

    split_all_kernel<<<SPLIT_BLOCKS, 256>>>((const float4*)x, (const float4*)Wq,
                                            (const float4*)Wk, (const float4*)Wv,
                                            (const float4*)Wo);

    dim3 gQKV(MTOT / BM, DMODEL / BN, 3);
    mma_gemm<0><<<gQKV, 256, GEMM_SMEM>>>(bq, bk, bv, nullptr);

    dim3 gAttn(SEQ / 64, BATCH * NHEADS);
    attn_mma_kernel<<<gAttn, 128, ATTN_SMEM>>>();

    dim3 gProj(MTOT / BM, DMODEL / BN);
    mma_gemm<1><<<gProj, 256, GEMM_SMEM>>>(bo, nullptr, nullptr, out);
}

// round 12
// speedup vs baseline: 1.1273x; 1.0421x over previous
#include <cuda_runtime.h>
#include <cuda_fp16.h>
#include <cstdint>
#include <math.h>

#define DMODEL 1024
#define NHEADS 16
#define DK     64
#define BATCH  4
#define SEQ    2048
#define MTOT   (BATCH*SEQ)   // 8192

#define QSCALE 0.1803368801111204f   // 0.125 * log2(e)

// ---------------- device scratch (allocation-free) ----------------
__device__ __half g_Qh[(size_t)MTOT * DMODEL];  // [B*H][S][DK]
__device__ __half g_Ql[(size_t)MTOT * DMODEL];
__device__ __half g_Kh[(size_t)MTOT * DMODEL];  // hi only
__device__ __half g_Vh[(size_t)MTOT * DMODEL];  // hi only
__device__ __half g_xh[(size_t)MTOT * DMODEL];
__device__ __half g_xl[(size_t)MTOT * DMODEL];
__device__ __half g_Wh[(size_t)4 * DMODEL * DMODEL];   // weights hi only
__device__ __half g_ah[(size_t)MTOT * DMODEL];  // attn out (hi only) [B,S,H*DK]

// ---------------- helpers ----------------
__device__ __forceinline__ uint32_t smem_u32(const void* p) {
    uint32_t a;
    asm("{ .reg .u64 t; cvta.to.shared.u64 t, %1; cvt.u32.u64 %0, t; }" : "=r"(a) : "l"(p));
    return a;
}
__device__ __forceinline__ uint32_t swz(uint32_t o) { return o ^ ((o >> 3) & 0x70); }

__device__ __forceinline__ void cp16(uint32_t dst, const void* src) {
    asm volatile("cp.async.cg.shared.global [%0], [%1], 16;" :: "r"(dst), "l"(src));
}
#define CP_COMMIT() asm volatile("cp.async.commit_group;" ::: "memory")
#define CP_WAIT0()  asm volatile("cp.async.wait_group 0;" ::: "memory")
#define CP_WAIT1()  asm volatile("cp.async.wait_group 1;" ::: "memory")

__device__ __forceinline__ void ldsm4(uint32_t* r, uint32_t a) {
    asm volatile("ldmatrix.sync.aligned.m8n8.x4.shared.b16 {%0,%1,%2,%3}, [%4];"
                 : "=r"(r[0]), "=r"(r[1]), "=r"(r[2]), "=r"(r[3]) : "r"(a));
}
__device__ __forceinline__ void ldsm4t(uint32_t* r, uint32_t a) {
    asm volatile("ldmatrix.sync.aligned.m8n8.x4.trans.shared.b16 {%0,%1,%2,%3}, [%4];"
                 : "=r"(r[0]), "=r"(r[1]), "=r"(r[2]), "=r"(r[3]) : "r"(a));
}
__device__ __forceinline__ void mma16816(float* c, const uint32_t* a, const uint32_t* b) {
    asm volatile("mma.sync.aligned.m16n8k16.row.col.f32.f16.f16.f32 "
                 "{%0,%1,%2,%3}, {%4,%5,%6,%7}, {%8,%9}, {%0,%1,%2,%3};"
                 : "+f"(c[0]), "+f"(c[1]), "+f"(c[2]), "+f"(c[3])
                 : "r"(a[0]), "r"(a[1]), "r"(a[2]), "r"(a[3]), "r"(b[0]), "r"(b[1]));
}

// Fast exp2 for t <= 0 (FMA pipe; err ~4e-5 rel)
__device__ __forceinline__ float exp2f_fast(float t) {
    t = fmaxf(t, -80.0f);
    float a = __fadd_rn(t, 12582912.0f);
    float r = __fsub_rn(t, __fsub_rn(a, 12582912.0f));
    float p = fmaf(r, 0.0096181291f, 0.0555041087f);
    p = fmaf(p, r, 0.2402265069f);
    p = fmaf(p, r, 0.6931471806f);
    p = fmaf(p, r, 1.0f);
    return __int_as_float(__float_as_int(p) + (__float_as_int(a) << 23));
}

__device__ __forceinline__ void split2(float x, float y, uint32_t& hi, uint32_t& lo) {
    __half hx = __float2half_rn(x), hy = __float2half_rn(y);
    __half2 h(hx, hy);
    hi = *reinterpret_cast<uint32_t*>(&h);
    __half2 l(__float2half_rn(x - __half2float(hx)),
              __float2half_rn(y - __half2float(hy)));
    lo = *reinterpret_cast<uint32_t*>(&l);
}
__device__ __forceinline__ uint32_t pack2(float x, float y) {
    __half2 h = __floats2half2_rn(x, y);
    return *reinterpret_cast<uint32_t*>(&h);
}

// ---------------- fused split: x -> hi/lo, Wq/Wk/Wv/Wo -> hi ----------------
#define N4X (MTOT * DMODEL / 4)        // 2097152
#define N4W (DMODEL * DMODEL / 4)      // 262144
#define SPLIT_BLOCKS ((N4X + 4 * N4W) / 256)

__global__ void split_all_kernel(const float4* __restrict__ x,
                                 const float4* __restrict__ Wq,
                                 const float4* __restrict__ Wk,
                                 const float4* __restrict__ Wv,
                                 const float4* __restrict__ Wo)
{
    int gi = blockIdx.x * 256 + threadIdx.x;
    if (gi < N4X) {
        float4 v = x[gi];
        uint32_t h0, l0, h1, l1;
        split2(v.x, v.y, h0, l0);
        split2(v.z, v.w, h1, l1);
        __half2* dh = reinterpret_cast<__half2*>(g_xh);
        __half2* dl = reinterpret_cast<__half2*>(g_xl);
        dh[2 * gi + 0] = *reinterpret_cast<__half2*>(&h0);
        dh[2 * gi + 1] = *reinterpret_cast<__half2*>(&h1);
        dl[2 * gi + 0] = *reinterpret_cast<__half2*>(&l0);
        dl[2 * gi + 1] = *reinterpret_cast<__half2*>(&l1);
    } else {
        int wi = gi - N4X;
        int z = wi / N4W;
        int i = wi - z * N4W;
        const float4* src = (z == 0) ? Wq : ((z == 1) ? Wk : ((z == 2) ? Wv : Wo));
        float4 v = src[i];
        __half2* dh = reinterpret_cast<__half2*>(g_Wh + (size_t)z * DMODEL * DMODEL);
        dh[2 * i + 0] = __half2(__float2half_rn(v.x), __float2half_rn(v.y));
        dh[2 * i + 1] = __half2(__float2half_rn(v.z), __float2half_rn(v.w));
    }
}

// ---------------- fp16 mma GEMM: C = A @ W^T + b ----------------------------
// MODE 0 = Q projection   : 2-term (xh+xl)·Wq, 2 stages x 48KB
// MODE 1 = K projection   : 1-term xh·Wk,      3 stages x 32KB
// MODE 2 = V projection   : 1-term xh·Wv,      3 stages x 32KB
// MODE 3 = output proj    : 1-term ah·Wo,      3 stages x 32KB
// All 96KB smem, 2 CTAs/SM.
#define BM 128
#define BN 128
#define CHUNKS 16
#define ATILE 16384
#define GEMM_SMEM 98304

template <int MODE>
__global__ __launch_bounds__(256, 2) void mma_gemm(
    const float* __restrict__ bias, float* __restrict__ outp)
{
    constexpr bool TWO = (MODE == 0);
    constexpr int NS = TWO ? 2 : 3;
    constexpr uint32_t STB = TWO ? (3 * ATILE) : (2 * ATILE);

    extern __shared__ char smg[];
    const uint32_t sbase = smem_u32(smg);
    const int tid = threadIdx.x, wid = tid >> 5, lane = tid & 31;
    const int warp_m = wid & 3, warp_n = wid >> 2;
    const int m0 = blockIdx.x * BM;
    const int n0 = blockIdx.y * BN;

    const __half* Ah = (MODE == 3) ? g_ah : g_xh;
    const __half* Al = g_xl;
    const __half* Bh = g_Wh + (size_t)MODE * DMODEL * DMODEL;

    float cacc[2][8][4];
#pragma unroll
    for (int mi = 0; mi < 2; mi++)
#pragma unroll
        for (int ni = 0; ni < 8; ni++)
#pragma unroll
            for (int q = 0; q < 4; q++) cacc[mi][ni][q] = 0.f;

    auto load_chunk = [&](int c, int stage) {
        const int kk = c * 64;
        const uint32_t sA = sbase + (uint32_t)stage * STB;
        const uint32_t sB = sA + (TWO ? 2u : 1u) * ATILE;
#pragma unroll
        for (int i = 0; i < 4; i++) {
            int u = tid + i * 256;       // 0..1023
            int row = u >> 3, c16 = u & 7;
            uint32_t so = swz((uint32_t)(row * 128 + c16 * 16));
            size_t go = (size_t)row * DMODEL + kk + c16 * 8;
            cp16(sA + so, Ah + (size_t)m0 * DMODEL + go);
            if (TWO) cp16(sA + ATILE + so, Al + (size_t)m0 * DMODEL + go);
            cp16(sB + so, Bh + (size_t)n0 * DMODEL + go);
        }
    };

    load_chunk(0, 0); CP_COMMIT();
    if (NS == 3) { load_chunk(1, 1); CP_COMMIT(); }

    for (int c = 0; c < CHUNKS; c++) {
        if (NS == 3) {
            if (c + 1 < CHUNKS) CP_WAIT1(); else CP_WAIT0();
            __syncthreads();
            if (c + 2 < CHUNKS) { load_chunk(c + 2, (c + 2) % 3); CP_COMMIT(); }
        } else {
            CP_WAIT0();
            __syncthreads();
            if (c + 1 < CHUNKS) { load_chunk(c + 1, (c + 1) & 1); CP_COMMIT(); }
        }

        const uint32_t sA = sbase + (uint32_t)(c % NS) * STB;
        const uint32_t sB = sA + (TWO ? 2u : 1u) * ATILE;

#pragma unroll
        for (int ks = 0; ks < 4; ks++) {
            uint32_t ah[2][4], al[2][4], b[4][4];
#pragma unroll
            for (int mi = 0; mi < 2; mi++) {
                int r = warp_m * 32 + mi * 16 + (lane & 15);
                uint32_t so = swz((uint32_t)(r * 128 + ks * 32 + ((lane >> 4) << 4)));
                ldsm4(ah[mi], sA + so);
                if (TWO) ldsm4(al[mi], sA + ATILE + so);
            }
#pragma unroll
            for (int nb = 0; nb < 4; nb++) {
                int n = warp_n * 64 + nb * 16 + (lane & 7) + ((lane >> 4) << 3);
                ldsm4(b[nb], sB + swz((uint32_t)(n * 128 + ks * 32 + (((lane >> 3) & 1) << 4))));
            }
#pragma unroll
            for (int mi = 0; mi < 2; mi++)
#pragma unroll
                for (int ni = 0; ni < 8; ni++) {
                    mma16816(cacc[mi][ni], ah[mi], &b[ni >> 1][(ni & 1) * 2]);
                    if (TWO) mma16816(cacc[mi][ni], al[mi], &b[ni >> 1][(ni & 1) * 2]);
                }
        }
    }

    const int row_base = m0 + warp_m * 32 + (lane >> 2);
    const int col_base = n0 + warp_n * 64 + (lane & 3) * 2;
#pragma unroll
    for (int ni = 0; ni < 8; ni++) {
        const int cc = col_base + ni * 8;
        const float bz0 = __ldg(&bias[cc]);
        const float bz1 = __ldg(&bias[cc + 1]);
#pragma unroll
        for (int mi = 0; mi < 2; mi++) {
#pragma unroll
            for (int half = 0; half < 2; half++) {
                const int m = row_base + mi * 16 + half * 8;
                float vx = cacc[mi][ni][half * 2 + 0] + bz0;
                float vy = cacc[mi][ni][half * 2 + 1] + bz1;
                if (MODE == 3) {
                    float2 v; v.x = vx; v.y = vy;
                    *reinterpret_cast<float2*>(&outp[(size_t)m * DMODEL + cc]) = v;
                } else {
                    const int bb = m >> 11, s = m & (SEQ - 1);
                    const int hd = cc >> 6, d = cc & 63;
                    size_t idx = (((size_t)(bb * NHEADS + hd)) * SEQ + s) * DK + d;
                    if (MODE == 0) {
                        vx *= QSCALE; vy *= QSCALE;
                        __half hx = __float2half_rn(vx), hy = __float2half_rn(vy);
                        *reinterpret_cast<__half2*>(g_Qh + idx) = __half2(hx, hy);
                        *reinterpret_cast<__half2*>(g_Ql + idx) =
                            __half2(__float2half_rn(vx - __half2float(hx)),
                                    __float2half_rn(vy - __half2float(hy)));
                    } else if (MODE == 1) {
                        *reinterpret_cast<__half2*>(g_Kh + idx) =
                            __half2(__float2half_rn(vx), __float2half_rn(vy));
                    } else {
                        *reinterpret_cast<__half2*>(g_Vh + idx) =
                            __half2(__float2half_rn(vx), __float2half_rn(vy));
                    }
                }
            }
        }
    }
}

// ---------------- tensor-core causal flash attention (fp16) -----------------
// 128 threads / 4 warps, Q tile 64 rows, KV tile 64, 3 KV stages of 16KB.
// Qh/Ql parked inside stage 1 during prologue (dead after fragment load).
// 48KB smem -> 4 CTAs/SM, no spills.
#define ASTAGE_BYTES 16384
#define ATTN_SMEM    (3 * ASTAGE_BYTES)   // 48KB

__global__ __launch_bounds__(128, 4) void attn_mma_kernel()
{
    extern __shared__ char smem[];
    const uint32_t sb = smem_u32(smem);
    const int tid = threadIdx.x, wid = tid >> 5, lane = tid & 31;
    const int qi = gridDim.x - 1 - blockIdx.x;   // long tiles first
    const int bh = blockIdx.y;
    const int q0 = qi * 64;
    const size_t base = (size_t)bh * SEQ * DK;

    const int nkt = qi + 1;
    auto load_kv = [&](int kt) {
        uint32_t st = sb + (uint32_t)(kt % 3) * ASTAGE_BYTES;
        const size_t ko = base + (size_t)kt * 64 * DK;
#pragma unroll
        for (int i = 0; i < 4; i++) {
            int u = tid + i * 128;        // 0..511
            int row = u >> 3, c16 = u & 7;
            uint32_t so = swz((uint32_t)(row * 128 + c16 * 16));
            cp16(st + so,        g_Kh + ko + (size_t)row * DK + c16 * 8);
            cp16(st + 8192 + so, g_Vh + ko + (size_t)row * DK + c16 * 8);
        }
    };

    // Prologue: Qh+Ql parked in stage 1 (16KB), kv0 -> stage 0; one group.
    const uint32_t sQh = sb + ASTAGE_BYTES;
    const uint32_t sQl = sQh + 8192;
#pragma unroll
    for (int i = 0; i < 4; i++) {
        int u = tid + i * 128;            // 0..511
        int row = u >> 3, c16 = u & 7;
        uint32_t so = swz((uint32_t)(row * 128 + c16 * 16));
        cp16(sQh + so, g_Qh + base + (size_t)(q0 + row) * DK + c16 * 8);
        cp16(sQl + so, g_Ql + base + (size_t)(q0 + row) * DK + c16 * 8);
    }
    load_kv(0);
    CP_COMMIT();
    CP_WAIT0();
    __syncthreads();

    uint32_t qh[4][4], ql[4][4];
    {
        int r = wid * 16 + (lane & 15);
        uint32_t half = (uint32_t)((lane >> 4) << 4);
#pragma unroll
        for (int kc = 0; kc < 4; kc++) {
            ldsm4(qh[kc], sQh + swz((uint32_t)(r * 128 + kc * 32) + half));
            ldsm4(ql[kc], sQl + swz((uint32_t)(r * 128 + kc * 32) + half));
        }
    }
    __syncthreads();   // all warps done reading Q before stage 1 reloads

    if (nkt > 1) { load_kv(1); CP_COMMIT(); }

    const int nrow = (lane & 7) + ((lane >> 4) << 3);
    const uint32_t koff = (uint32_t)(((lane >> 3) & 1) << 4);
    const int vkey = ((lane >> 3) & 1) * 8 + (lane & 7);
    const uint32_t vdk = (uint32_t)(((lane >> 4) << 3) * 2);

    float o[8][4];
#pragma unroll
    for (int nt = 0; nt < 8; nt++)
#pragma unroll
        for (int q = 0; q < 4; q++) o[nt][q] = 0.f;
    float m0v = -3.0e38f, m1v = -3.0e38f, l0 = 0.f, l1 = 0.f;

    const int rq = q0 + wid * 16 + (lane >> 2);

    for (int kt = 0; kt < nkt; kt++) {
        if (kt > 0) {
            // kv(kt+1) is the only possibly-newer outstanding group.
            if (kt + 1 < nkt) CP_WAIT1(); else CP_WAIT0();
            __syncthreads();
        }
        if (kt + 2 < nkt) { load_kv(kt + 2); CP_COMMIT(); }

        const uint32_t st = sb + (uint32_t)(kt % 3) * ASTAGE_BYTES;

        // ---- S[64q x 64k] = (Qh+Ql)·Kh ----
        float s[8][4];
#pragma unroll
        for (int nt = 0; nt < 8; nt++)
#pragma unroll
            for (int q = 0; q < 4; q++) s[nt][q] = 0.f;

#pragma unroll
        for (int kc = 0; kc < 4; kc++) {
            uint32_t kb[16];
#pragma unroll
            for (int nb = 0; nb < 4; nb++)
                ldsm4(kb + nb * 4, st + swz((uint32_t)((nb * 16 + nrow) * 128 + kc * 32) + koff));
#pragma unroll
            for (int nt = 0; nt < 8; nt++) mma16816(s[nt], qh[kc], &kb[nt * 2]);
#pragma unroll
            for (int nt = 0; nt < 8; nt++) mma16816(s[nt], ql[kc], &kb[nt * 2]);
        }

        // ---- causal mask (diagonal tile only) ----
        if (kt == qi) {
            const int cb = kt * 64 + 2 * (lane & 3);
#pragma unroll
            for (int nt = 0; nt < 8; nt++) {
                int c0 = cb + 8 * nt;
                if (c0     > rq)     s[nt][0] = -1.0e30f;
                if (c0 + 1 > rq)     s[nt][1] = -1.0e30f;
                if (c0     > rq + 8) s[nt][2] = -1.0e30f;
                if (c0 + 1 > rq + 8) s[nt][3] = -1.0e30f;
            }
        }

        // ---- online softmax ----
        float mx0 = -3.0e38f, mx1 = -3.0e38f;
#pragma unroll
        for (int nt = 0; nt < 8; nt++) {
            mx0 = fmaxf(mx0, fmaxf(s[nt][0], s[nt][1]));
            mx1 = fmaxf(mx1, fmaxf(s[nt][2], s[nt][3]));
        }
        mx0 = fmaxf(mx0, __shfl_xor_sync(0xFFFFFFFFu, mx0, 1));
        mx0 = fmaxf(mx0, __shfl_xor_sync(0xFFFFFFFFu, mx0, 2));
        mx1 = fmaxf(mx1, __shfl_xor_sync(0xFFFFFFFFu, mx1, 1));
        mx1 = fmaxf(mx1, __shfl_xor_sync(0xFFFFFFFFu, mx1, 2));
        const float mn0 = fmaxf(m0v, mx0), mn1 = fmaxf(m1v, mx1);
        const float f0 = exp2f_fast(m0v - mn0), f1 = exp2f_fast(m1v - mn1);
        m0v = mn0; m1v = mn1;

        float sum0 = 0.f, sum1 = 0.f;
        uint32_t ph[4][4];
#pragma unroll
        for (int kc = 0; kc < 4; kc++) {
            float e00 = exp2f_fast(s[2*kc][0]   - mn0);
            float e01 = exp2f_fast(s[2*kc][1]   - mn0);
            float e10 = exp2f_fast(s[2*kc][2]   - mn1);
            float e11 = exp2f_fast(s[2*kc][3]   - mn1);
            float e20 = exp2f_fast(s[2*kc+1][0] - mn0);
            float e21 = exp2f_fast(s[2*kc+1][1] - mn0);
            float e30 = exp2f_fast(s[2*kc+1][2] - mn1);
            float e31 = exp2f_fast(s[2*kc+1][3] - mn1);
            sum0 += (e00 + e01) + (e20 + e21);
            sum1 += (e10 + e11) + (e30 + e31);
            ph[kc][0] = pack2(e00, e01);
            ph[kc][1] = pack2(e10, e11);
            ph[kc][2] = pack2(e20, e21);
            ph[kc][3] = pack2(e30, e31);
        }
        sum0 += __shfl_xor_sync(0xFFFFFFFFu, sum0, 1);
        sum0 += __shfl_xor_sync(0xFFFFFFFFu, sum0, 2);
        sum1 += __shfl_xor_sync(0xFFFFFFFFu, sum1, 1);
        sum1 += __shfl_xor_sync(0xFFFFFFFFu, sum1, 2);
        l0 = l0 * f0 + sum0;
        l1 = l1 * f1 + sum1;

#pragma unroll
        for (int nt = 0; nt < 8; nt++) {
            o[nt][0] *= f0; o[nt][1] *= f0;
            o[nt][2] *= f1; o[nt][3] *= f1;
        }

        // ---- O += Ph·Vh ----
        const uint32_t stv = st + 8192;
#pragma unroll
        for (int kc = 0; kc < 4; kc++) {
            uint32_t vb[16];
#pragma unroll
            for (int p4 = 0; p4 < 4; p4++)
                ldsm4t(vb + p4 * 4, stv +
                       swz((uint32_t)((kc * 16 + vkey) * 128 + p4 * 32) + vdk));
#pragma unroll
            for (int nt = 0; nt < 8; nt++) mma16816(o[nt], ph[kc], &vb[nt * 2]);
        }
    }

    // ---- epilogue: normalize, store fp16 hi to [B,S,H*DK] ----
    const float inv0 = 1.0f / l0, inv1 = 1.0f / l1;
    const int b = bh >> 4, hd = bh & 15;
    const int dkb = 2 * (lane & 3);
#pragma unroll
    for (int nt = 0; nt < 8; nt++) {
        const int d = hd * 64 + dkb + 8 * nt;
        size_t i0 = ((size_t)b * SEQ + rq) * DMODEL + d;
        size_t i1 = ((size_t)b * SEQ + rq + 8) * DMODEL + d;
        uint32_t p0 = pack2(o[nt][0] * inv0, o[nt][1] * inv0);
        uint32_t p1 = pack2(o[nt][2] * inv1, o[nt][3] * inv1);
        *reinterpret_cast<uint32_t*>(g_ah + i0) = p0;
        *reinterpret_cast<uint32_t*>(g_ah + i1) = p1;
    }
}

// ---------------------------------------------------------------------------
extern "C" void kernel_launch(void* const* d_in, const int* in_sizes, int n_in,
                              void* d_out, int out_size)
{
    const float* x  = (const float*)d_in[0];
    const float* Wq = (const float*)d_in[1];
    const float* bq = (const float*)d_in[2];
    const float* Wk = (const float*)d_in[3];
    const float* bk = (const float*)d_in[4];
    const float* Wv = (const float*)d_in[5];
    const float* bv = (const float*)d_in[6];
    const float* Wo = (const float*)d_in[7];
    const float* bo = (const float*)d_in[8];
    float* out = (float*)d_out;
    (void)in_sizes; (void)n_in; (void)out_size;

    static bool attr_done = false;
    if (!attr_done) {
        cudaFuncSetAttribute(mma_gemm<0>, cudaFuncAttributeMaxDynamicSharedMemorySize, GEMM_SMEM);
        cudaFuncSetAttribute(mma_gemm<1>, cudaFuncAttributeMaxDynamicSharedMemorySize, GEMM_SMEM);
        cudaFuncSetAttribute(mma_gemm<2>, cudaFuncAttributeMaxDynamicSharedMemorySize, GEMM_SMEM);
        cudaFuncSetAttribute(mma_gemm<3>, cudaFuncAttributeMaxDynamicSharedMemorySize, GEMM_SMEM);
        cudaFuncSetAttribute(attn_mma_kernel, cudaFuncAttributeMaxDynamicSharedMemorySize, ATTN_SMEM);
        attr_done = true;
    }

    split_all_kernel<<<SPLIT_BLOCKS, 256>>>((const float4*)x, (const float4*)Wq,
                                            (const float4*)Wk, (const float4*)Wv,
                                            (const float4*)Wo);

    dim3 gG(MTOT / BM, DMODEL / BN);
    mma_gemm<0><<<gG, 256, GEMM_SMEM>>>(bq, nullptr);
    mma_gemm<1><<<gG, 256, GEMM_SMEM>>>(bk, nullptr);
    mma_gemm<2><<<gG, 256, GEMM_SMEM>>>(bv, nullptr);

    dim3 gAttn(SEQ / 64, BATCH * NHEADS);
    attn_mma_kernel<<<gAttn, 128, ATTN_SMEM>>>();

    mma_gemm<3><<<gG, 256, GEMM_SMEM>>>(bo, out);
}

// round 13
// speedup vs baseline: 1.3547x; 1.2016x over previous
#include <cuda_runtime.h>
#include <cuda_fp16.h>
#include <cstdint>
#include <math.h>

#define DMODEL 1024
#define NHEADS 16
#define DK     64
#define BATCH  4
#define SEQ    2048
#define MTOT   (BATCH*SEQ)   // 8192

#define QSCALE 0.1803368801111204f   // 0.125 * log2(e)

// ---------------- device scratch (allocation-free) ----------------
__device__ __half g_Qh[(size_t)MTOT * DMODEL];  // [B*H][S][DK]
__device__ __half g_Kh[(size_t)MTOT * DMODEL];
__device__ __half g_Vh[(size_t)MTOT * DMODEL];
__device__ __half g_xh[(size_t)MTOT * DMODEL];
__device__ __half g_Wh[(size_t)4 * DMODEL * DMODEL];
__device__ __half g_ah[(size_t)MTOT * DMODEL];  // attn out [B,S,H*DK]

// ---------------- helpers ----------------
__device__ __forceinline__ uint32_t smem_u32(const void* p) {
    uint32_t a;
    asm("{ .reg .u64 t; cvta.to.shared.u64 t, %1; cvt.u32.u64 %0, t; }" : "=r"(a) : "l"(p));
    return a;
}
__device__ __forceinline__ uint32_t swz(uint32_t o) { return o ^ ((o >> 3) & 0x70); }

__device__ __forceinline__ void cp16(uint32_t dst, const void* src) {
    asm volatile("cp.async.cg.shared.global [%0], [%1], 16;" :: "r"(dst), "l"(src));
}
#define CP_COMMIT() asm volatile("cp.async.commit_group;" ::: "memory")
#define CP_WAIT0()  asm volatile("cp.async.wait_group 0;" ::: "memory")
#define CP_WAIT1()  asm volatile("cp.async.wait_group 1;" ::: "memory")

__device__ __forceinline__ void ldsm4(uint32_t* r, uint32_t a) {
    asm volatile("ldmatrix.sync.aligned.m8n8.x4.shared.b16 {%0,%1,%2,%3}, [%4];"
                 : "=r"(r[0]), "=r"(r[1]), "=r"(r[2]), "=r"(r[3]) : "r"(a));
}
__device__ __forceinline__ void ldsm4t(uint32_t* r, uint32_t a) {
    asm volatile("ldmatrix.sync.aligned.m8n8.x4.trans.shared.b16 {%0,%1,%2,%3}, [%4];"
                 : "=r"(r[0]), "=r"(r[1]), "=r"(r[2]), "=r"(r[3]) : "r"(a));
}
__device__ __forceinline__ void mma16816(float* c, const uint32_t* a, const uint32_t* b) {
    asm volatile("mma.sync.aligned.m16n8k16.row.col.f32.f16.f16.f32 "
                 "{%0,%1,%2,%3}, {%4,%5,%6,%7}, {%8,%9}, {%0,%1,%2,%3};"
                 : "+f"(c[0]), "+f"(c[1]), "+f"(c[2]), "+f"(c[3])
                 : "r"(a[0]), "r"(a[1]), "r"(a[2]), "r"(a[3]), "r"(b[0]), "r"(b[1]));
}

// Fast exp2 for t <= 0 (FMA pipe; err ~4e-5 rel)
__device__ __forceinline__ float exp2f_fast(float t) {
    t = fmaxf(t, -80.0f);
    float a = __fadd_rn(t, 12582912.0f);
    float r = __fsub_rn(t, __fsub_rn(a, 12582912.0f));
    float p = fmaf(r, 0.0096181291f, 0.0555041087f);
    p = fmaf(p, r, 0.2402265069f);
    p = fmaf(p, r, 0.6931471806f);
    p = fmaf(p, r, 1.0f);
    return __int_as_float(__float_as_int(p) + (__float_as_int(a) << 23));
}

__device__ __forceinline__ uint32_t pack2(float x, float y) {
    __half2 h = __floats2half2_rn(x, y);
    return *reinterpret_cast<uint32_t*>(&h);
}

// ---------------- fused split: x, Wq/Wk/Wv/Wo -> fp16 hi ----------------
#define N4X (MTOT * DMODEL / 4)        // 2097152
#define N4W (DMODEL * DMODEL / 4)      // 262144
#define SPLIT_BLOCKS ((N4X + 4 * N4W) / 256)

__global__ void split_all_kernel(const float4* __restrict__ x,
                                 const float4* __restrict__ Wq,
                                 const float4* __restrict__ Wk,
                                 const float4* __restrict__ Wv,
                                 const float4* __restrict__ Wo)
{
    int gi = blockIdx.x * 256 + threadIdx.x;
    const float4* src;
    __half2* dh;
    int i;
    if (gi < N4X) {
        src = x; i = gi;
        dh = reinterpret_cast<__half2*>(g_xh);
    } else {
        int wi = gi - N4X;
        int z = wi / N4W;
        i = wi - z * N4W;
        src = (z == 0) ? Wq : ((z == 1) ? Wk : ((z == 2) ? Wv : Wo));
        dh = reinterpret_cast<__half2*>(g_Wh + (size_t)z * DMODEL * DMODEL);
    }
    float4 v = src[i];
    dh[2 * i + 0] = __half2(__float2half_rn(v.x), __float2half_rn(v.y));
    dh[2 * i + 1] = __half2(__float2half_rn(v.z), __float2half_rn(v.w));
}

// ---------------- fp16 mma GEMM: C = A @ W^T + b (all 1-term) ---------------
// 3 stages x 32KB = 96KB smem, 2 CTAs/SM.
#define BM 128
#define BN 128
#define CHUNKS 16
#define ATILE 16384
#define GEMM_STB (2 * ATILE)
#define GEMM_SMEM (3 * GEMM_STB)   // 96KB

template <int MODE>  // 0=Q 1=K 2=V 3=proj
__global__ __launch_bounds__(256, 2) void mma_gemm(
    const float* __restrict__ bias, float* __restrict__ outp)
{
    extern __shared__ char smg[];
    const uint32_t sbase = smem_u32(smg);
    const int tid = threadIdx.x, wid = tid >> 5, lane = tid & 31;
    const int warp_m = wid & 3, warp_n = wid >> 2;
    const int m0 = blockIdx.x * BM;
    const int n0 = blockIdx.y * BN;

    const __half* Ah = (MODE == 3) ? g_ah : g_xh;
    const __half* Bh = g_Wh + (size_t)MODE * DMODEL * DMODEL;

    float cacc[2][8][4];
#pragma unroll
    for (int mi = 0; mi < 2; mi++)
#pragma unroll
        for (int ni = 0; ni < 8; ni++)
#pragma unroll
            for (int q = 0; q < 4; q++) cacc[mi][ni][q] = 0.f;

    auto load_chunk = [&](int c, int stage) {
        const int kk = c * 64;
        const uint32_t sA = sbase + (uint32_t)stage * GEMM_STB;
        const uint32_t sB = sA + ATILE;
#pragma unroll
        for (int i = 0; i < 4; i++) {
            int u = tid + i * 256;       // 0..1023
            int row = u >> 3, c16 = u & 7;
            uint32_t so = swz((uint32_t)(row * 128 + c16 * 16));
            size_t go = (size_t)row * DMODEL + kk + c16 * 8;
            cp16(sA + so, Ah + (size_t)m0 * DMODEL + go);
            cp16(sB + so, Bh + (size_t)n0 * DMODEL + go);
        }
    };

    load_chunk(0, 0); CP_COMMIT();
    load_chunk(1, 1); CP_COMMIT();

    for (int c = 0; c < CHUNKS; c++) {
        if (c + 1 < CHUNKS) CP_WAIT1(); else CP_WAIT0();
        __syncthreads();
        if (c + 2 < CHUNKS) { load_chunk(c + 2, (c + 2) % 3); CP_COMMIT(); }

        const uint32_t sA = sbase + (uint32_t)(c % 3) * GEMM_STB;
        const uint32_t sB = sA + ATILE;

#pragma unroll
        for (int ks = 0; ks < 4; ks++) {
            uint32_t ah[2][4], b[4][4];
#pragma unroll
            for (int mi = 0; mi < 2; mi++) {
                int r = warp_m * 32 + mi * 16 + (lane & 15);
                ldsm4(ah[mi], sA + swz((uint32_t)(r * 128 + ks * 32 + ((lane >> 4) << 4))));
            }
#pragma unroll
            for (int nb = 0; nb < 4; nb++) {
                int n = warp_n * 64 + nb * 16 + (lane & 7) + ((lane >> 4) << 3);
                ldsm4(b[nb], sB + swz((uint32_t)(n * 128 + ks * 32 + (((lane >> 3) & 1) << 4))));
            }
#pragma unroll
            for (int mi = 0; mi < 2; mi++)
#pragma unroll
                for (int ni = 0; ni < 8; ni++)
                    mma16816(cacc[mi][ni], ah[mi], &b[ni >> 1][(ni & 1) * 2]);
        }
    }

    const int row_base = m0 + warp_m * 32 + (lane >> 2);
    const int col_base = n0 + warp_n * 64 + (lane & 3) * 2;
#pragma unroll
    for (int ni = 0; ni < 8; ni++) {
        const int cc = col_base + ni * 8;
        const float bz0 = __ldg(&bias[cc]);
        const float bz1 = __ldg(&bias[cc + 1]);
#pragma unroll
        for (int mi = 0; mi < 2; mi++) {
#pragma unroll
            for (int half = 0; half < 2; half++) {
                const int m = row_base + mi * 16 + half * 8;
                float vx = cacc[mi][ni][half * 2 + 0] + bz0;
                float vy = cacc[mi][ni][half * 2 + 1] + bz1;
                if (MODE == 3) {
                    float2 v; v.x = vx; v.y = vy;
                    *reinterpret_cast<float2*>(&outp[(size_t)m * DMODEL + cc]) = v;
                } else {
                    const int bb = m >> 11, s = m & (SEQ - 1);
                    const int hd = cc >> 6, d = cc & 63;
                    size_t idx = (((size_t)(bb * NHEADS + hd)) * SEQ + s) * DK + d;
                    if (MODE == 0) { vx *= QSCALE; vy *= QSCALE; }
                    __half* dst = (MODE == 0) ? g_Qh : ((MODE == 1) ? g_Kh : g_Vh);
                    *reinterpret_cast<__half2*>(dst + idx) =
                        __half2(__float2half_rn(vx), __float2half_rn(vy));
                }
            }
        }
    }
}

// ---------------- tensor-core causal flash attention (fp16, 1-term) ---------
// 128 threads / 4 warps, Q tile 64 rows, KV tile 64, 3 KV stages of 16KB.
// Q parked inside stage 1 during prologue. 48KB smem -> 4 CTAs/SM.
#define ASTAGE_BYTES 16384
#define ATTN_SMEM    (3 * ASTAGE_BYTES)   // 48KB

__global__ __launch_bounds__(128, 4) void attn_mma_kernel()
{
    extern __shared__ char smem[];
    const uint32_t sb = smem_u32(smem);
    const int tid = threadIdx.x, wid = tid >> 5, lane = tid & 31;
    const int qi = gridDim.x - 1 - blockIdx.x;   // long tiles first
    const int bh = blockIdx.y;
    const int q0 = qi * 64;
    const size_t base = (size_t)bh * SEQ * DK;

    const int nkt = qi + 1;
    auto load_kv = [&](int kt) {
        uint32_t st = sb + (uint32_t)(kt % 3) * ASTAGE_BYTES;
        const size_t ko = base + (size_t)kt * 64 * DK;
#pragma unroll
        for (int i = 0; i < 4; i++) {
            int u = tid + i * 128;        // 0..511
            int row = u >> 3, c16 = u & 7;
            uint32_t so = swz((uint32_t)(row * 128 + c16 * 16));
            cp16(st + so,        g_Kh + ko + (size_t)row * DK + c16 * 8);
            cp16(st + 8192 + so, g_Vh + ko + (size_t)row * DK + c16 * 8);
        }
    };

    // Prologue: Qh parked in stage 1 (8KB), kv0 -> stage 0; one group.
    const uint32_t sQh = sb + ASTAGE_BYTES;
#pragma unroll
    for (int i = 0; i < 4; i++) {
        int u = tid * 4 + i;              // 0..511 (consecutive per thread)
        int row = u >> 3, c16 = u & 7;
        if (i < 4 && u < 512) {}
        uint32_t so = swz((uint32_t)(row * 128 + c16 * 16));
        (void)so;
    }
    // simple strided Q load: 512 x16B slots over 128 threads
#pragma unroll
    for (int i = 0; i < 4; i++) {
        int u = tid + i * 128;            // 0..511
        int row = u >> 3, c16 = u & 7;
        uint32_t so = swz((uint32_t)(row * 128 + c16 * 16));
        cp16(sQh + so, g_Qh + base + (size_t)(q0 + row) * DK + c16 * 8);
    }
    load_kv(0);
    CP_COMMIT();
    CP_WAIT0();
    __syncthreads();

    uint32_t qh[4][4];
    {
        int r = wid * 16 + (lane & 15);
        uint32_t half = (uint32_t)((lane >> 4) << 4);
#pragma unroll
        for (int kc = 0; kc < 4; kc++)
            ldsm4(qh[kc], sQh + swz((uint32_t)(r * 128 + kc * 32) + half));
    }
    __syncthreads();   // Q reads done before stage 1 reloads

    if (nkt > 1) { load_kv(1); CP_COMMIT(); }

    const int nrow = (lane & 7) + ((lane >> 4) << 3);
    const uint32_t koff = (uint32_t)(((lane >> 3) & 1) << 4);
    const int vkey = ((lane >> 3) & 1) * 8 + (lane & 7);
    const uint32_t vdk = (uint32_t)(((lane >> 4) << 3) * 2);

    float o[8][4];
#pragma unroll
    for (int nt = 0; nt < 8; nt++)
#pragma unroll
        for (int q = 0; q < 4; q++) o[nt][q] = 0.f;
    float m0v = -3.0e38f, m1v = -3.0e38f, l0 = 0.f, l1 = 0.f;

    const int rq = q0 + wid * 16 + (lane >> 2);

    for (int kt = 0; kt < nkt; kt++) {
        if (kt > 0) {
            if (kt + 1 < nkt) CP_WAIT1(); else CP_WAIT0();
            __syncthreads();
        }
        if (kt + 2 < nkt) { load_kv(kt + 2); CP_COMMIT(); }

        const uint32_t st = sb + (uint32_t)(kt % 3) * ASTAGE_BYTES;

        // ---- S[64q x 64k] = Qh·Kh ----
        float s[8][4];
#pragma unroll
        for (int nt = 0; nt < 8; nt++)
#pragma unroll
            for (int q = 0; q < 4; q++) s[nt][q] = 0.f;

#pragma unroll
        for (int kc = 0; kc < 4; kc++) {
            uint32_t kb[16];
#pragma unroll
            for (int nb = 0; nb < 4; nb++)
                ldsm4(kb + nb * 4, st + swz((uint32_t)((nb * 16 + nrow) * 128 + kc * 32) + koff));
#pragma unroll
            for (int nt = 0; nt < 8; nt++) mma16816(s[nt], qh[kc], &kb[nt * 2]);
        }

        // ---- causal mask (diagonal tile only) ----
        if (kt == qi) {
            const int cb = kt * 64 + 2 * (lane & 3);
#pragma unroll
            for (int nt = 0; nt < 8; nt++) {
                int c0 = cb + 8 * nt;
                if (c0     > rq)     s[nt][0] = -1.0e30f;
                if (c0 + 1 > rq)     s[nt][1] = -1.0e30f;
                if (c0     > rq + 8) s[nt][2] = -1.0e30f;
                if (c0 + 1 > rq + 8) s[nt][3] = -1.0e30f;
            }
        }

        // ---- online softmax ----
        float mx0 = -3.0e38f, mx1 = -3.0e38f;
#pragma unroll
        for (int nt = 0; nt < 8; nt++) {
            mx0 = fmaxf(mx0, fmaxf(s[nt][0], s[nt][1]));
            mx1 = fmaxf(mx1, fmaxf(s[nt][2], s[nt][3]));
        }
        mx0 = fmaxf(mx0, __shfl_xor_sync(0xFFFFFFFFu, mx0, 1));
        mx0 = fmaxf(mx0, __shfl_xor_sync(0xFFFFFFFFu, mx0, 2));
        mx1 = fmaxf(mx1, __shfl_xor_sync(0xFFFFFFFFu, mx1, 1));
        mx1 = fmaxf(mx1, __shfl_xor_sync(0xFFFFFFFFu, mx1, 2));
        const float mn0 = fmaxf(m0v, mx0), mn1 = fmaxf(m1v, mx1);
        const float f0 = exp2f_fast(m0v - mn0), f1 = exp2f_fast(m1v - mn1);
        m0v = mn0; m1v = mn1;

        float sum0 = 0.f, sum1 = 0.f;
        uint32_t ph[4][4];
#pragma unroll
        for (int kc = 0; kc < 4; kc++) {
            float e00 = exp2f_fast(s[2*kc][0]   - mn0);
            float e01 = exp2f_fast(s[2*kc][1]   - mn0);
            float e10 = exp2f_fast(s[2*kc][2]   - mn1);
            float e11 = exp2f_fast(s[2*kc][3]   - mn1);
            float e20 = exp2f_fast(s[2*kc+1][0] - mn0);
            float e21 = exp2f_fast(s[2*kc+1][1] - mn0);
            float e30 = exp2f_fast(s[2*kc+1][2] - mn1);
            float e31 = exp2f_fast(s[2*kc+1][3] - mn1);
            sum0 += (e00 + e01) + (e20 + e21);
            sum1 += (e10 + e11) + (e30 + e31);
            ph[kc][0] = pack2(e00, e01);
            ph[kc][1] = pack2(e10, e11);
            ph[kc][2] = pack2(e20, e21);
            ph[kc][3] = pack2(e30, e31);
        }
        sum0 += __shfl_xor_sync(0xFFFFFFFFu, sum0, 1);
        sum0 += __shfl_xor_sync(0xFFFFFFFFu, sum0, 2);
        sum1 += __shfl_xor_sync(0xFFFFFFFFu, sum1, 1);
        sum1 += __shfl_xor_sync(0xFFFFFFFFu, sum1, 2);
        l0 = l0 * f0 + sum0;
        l1 = l1 * f1 + sum1;

#pragma unroll
        for (int nt = 0; nt < 8; nt++) {
            o[nt][0] *= f0; o[nt][1] *= f0;
            o[nt][2] *= f1; o[nt][3] *= f1;
        }

        // ---- O += Ph·Vh ----
        const uint32_t stv = st + 8192;
#pragma unroll
        for (int kc = 0; kc < 4; kc++) {
            uint32_t vb[16];
#pragma unroll
            for (int p4 = 0; p4 < 4; p4++)
                ldsm4t(vb + p4 * 4, stv +
                       swz((uint32_t)((kc * 16 + vkey) * 128 + p4 * 32) + vdk));
#pragma unroll
            for (int nt = 0; nt < 8; nt++) mma16816(o[nt], ph[kc], &vb[nt * 2]);
        }
    }

    // ---- epilogue: normalize, store fp16 hi to [B,S,H*DK] ----
    const float inv0 = 1.0f / l0, inv1 = 1.0f / l1;
    const int b = bh >> 4, hd = bh & 15;
    const int dkb = 2 * (lane & 3);
#pragma unroll
    for (int nt = 0; nt < 8; nt++) {
        const int d = hd * 64 + dkb + 8 * nt;
        size_t i0 = ((size_t)b * SEQ + rq) * DMODEL + d;
        size_t i1 = ((size_t)b * SEQ + rq + 8) * DMODEL + d;
        uint32_t p0 = pack2(o[nt][0] * inv0, o[nt][1] * inv0);
        uint32_t p1 = pack2(o[nt][2] * inv1, o[nt][3] * inv1);
        *reinterpret_cast<uint32_t*>(g_ah + i0) = p0;
        *reinterpret_cast<uint32_t*>(g_ah + i1) = p1;
    }
}

// ---------------------------------------------------------------------------
extern "C" void kernel_launch(void* const* d_in, const int* in_sizes, int n_in,
                              void* d_out, int out_size)
{
    const float* x  = (const float*)d_in[0];
    const float* Wq = (const float*)d_in[1];
    const float* bq = (const float*)d_in[2];
    const float* Wk = (const float*)d_in[3];
    const float* bk = (const float*)d_in[4];
    const float* Wv = (const float*)d_in[5];
    const float* bv = (const float*)d_in[6];
    const float* Wo = (const float*)d_in[7];
    const float* bo = (const float*)d_in[8];
    float* out = (float*)d_out;
    (void)in_sizes; (void)n_in; (void)out_size;

    static bool attr_done = false;
    if (!attr_done) {
        cudaFuncSetAttribute(mma_gemm<0>, cudaFuncAttributeMaxDynamicSharedMemorySize, GEMM_SMEM);
        cudaFuncSetAttribute(mma_gemm<1>, cudaFuncAttributeMaxDynamicSharedMemorySize, GEMM_SMEM);
        cudaFuncSetAttribute(mma_gemm<2>, cudaFuncAttributeMaxDynamicSharedMemorySize, GEMM_SMEM);
        cudaFuncSetAttribute(mma_gemm<3>, cudaFuncAttributeMaxDynamicSharedMemorySize, GEMM_SMEM);
        cudaFuncSetAttribute(attn_mma_kernel, cudaFuncAttributeMaxDynamicSharedMemorySize, ATTN_SMEM);
        attr_done = true;
    }

    split_all_kernel<<<SPLIT_BLOCKS, 256>>>((const float4*)x, (const float4*)Wq,
                                            (const float4*)Wk, (const float4*)Wv,
                                            (const float4*)Wo);

    dim3 gG(MTOT / BM, DMODEL / BN);
    mma_gemm<0><<<gG, 256, GEMM_SMEM>>>(bq, nullptr);
    mma_gemm<1><<<gG, 256, GEMM_SMEM>>>(bk, nullptr);
    mma_gemm<2><<<gG, 256, GEMM_SMEM>>>(bv, nullptr);

    dim3 gAttn(SEQ / 64, BATCH * NHEADS);
    attn_mma_kernel<<<gAttn, 128, ATTN_SMEM>>>();

    mma_gemm<3><<<gG, 256, GEMM_SMEM>>>(bo, out);
}

// round 14
// speedup vs baseline: 1.3878x; 1.0245x over previous
#include <cuda_runtime.h>
#include <cuda_fp16.h>
#include <cstdint>
#include <math.h>

#define DMODEL 1024
#define NHEADS 16
#define DK     64
#define BATCH  4
#define SEQ    2048
#define MTOT   (BATCH*SEQ)   // 8192

#define QSCALE 0.1803368801111204f   // 0.125 * log2(e)

// ---------------- device scratch (allocation-free) ----------------
__device__ __half g_Qh[(size_t)MTOT * DMODEL];  // [B*H][S][DK]
__device__ __half g_Kh[(size_t)MTOT * DMODEL];
__device__ __half g_Vh[(size_t)MTOT * DMODEL];
__device__ __half g_xh[(size_t)MTOT * DMODEL];
__device__ __half g_Wh[(size_t)4 * DMODEL * DMODEL];
__device__ __half g_ah[(size_t)MTOT * DMODEL];  // attn out [B,S,H*DK]

// ---------------- helpers ----------------
__device__ __forceinline__ uint32_t smem_u32(const void* p) {
    uint32_t a;
    asm("{ .reg .u64 t; cvta.to.shared.u64 t, %1; cvt.u32.u64 %0, t; }" : "=r"(a) : "l"(p));
    return a;
}
__device__ __forceinline__ uint32_t swz(uint32_t o) { return o ^ ((o >> 3) & 0x70); }

__device__ __forceinline__ void cp16(uint32_t dst, const void* src) {
    asm volatile("cp.async.cg.shared.global [%0], [%1], 16;" :: "r"(dst), "l"(src));
}
#define CP_COMMIT() asm volatile("cp.async.commit_group;" ::: "memory")
#define CP_WAIT0()  asm volatile("cp.async.wait_group 0;" ::: "memory")
#define CP_WAIT1()  asm volatile("cp.async.wait_group 1;" ::: "memory")

__device__ __forceinline__ void ldsm4(uint32_t* r, uint32_t a) {
    asm volatile("ldmatrix.sync.aligned.m8n8.x4.shared.b16 {%0,%1,%2,%3}, [%4];"
                 : "=r"(r[0]), "=r"(r[1]), "=r"(r[2]), "=r"(r[3]) : "r"(a));
}
__device__ __forceinline__ void ldsm4t(uint32_t* r, uint32_t a) {
    asm volatile("ldmatrix.sync.aligned.m8n8.x4.trans.shared.b16 {%0,%1,%2,%3}, [%4];"
                 : "=r"(r[0]), "=r"(r[1]), "=r"(r[2]), "=r"(r[3]) : "r"(a));
}
__device__ __forceinline__ void mma16816(float* c, const uint32_t* a, const uint32_t* b) {
    asm volatile("mma.sync.aligned.m16n8k16.row.col.f32.f16.f16.f32 "
                 "{%0,%1,%2,%3}, {%4,%5,%6,%7}, {%8,%9}, {%0,%1,%2,%3};"
                 : "+f"(c[0]), "+f"(c[1]), "+f"(c[2]), "+f"(c[3])
                 : "r"(a[0]), "r"(a[1]), "r"(a[2]), "r"(a[3]), "r"(b[0]), "r"(b[1]));
}

// Fast exp2 for t <= 0 (FMA pipe; err ~4e-5 rel)
__device__ __forceinline__ float exp2f_fast(float t) {
    t = fmaxf(t, -80.0f);
    float a = __fadd_rn(t, 12582912.0f);
    float r = __fsub_rn(t, __fsub_rn(a, 12582912.0f));
    float p = fmaf(r, 0.0096181291f, 0.0555041087f);
    p = fmaf(p, r, 0.2402265069f);
    p = fmaf(p, r, 0.6931471806f);
    p = fmaf(p, r, 1.0f);
    return __int_as_float(__float_as_int(p) + (__float_as_int(a) << 23));
}

__device__ __forceinline__ uint32_t pack2(float x, float y) {
    __half2 h = __floats2half2_rn(x, y);
    return *reinterpret_cast<uint32_t*>(&h);
}

// ---------------- fused split: x, Wq/Wk/Wv/Wo -> fp16 ----------------
#define N4X (MTOT * DMODEL / 4)        // 2097152
#define N4W (DMODEL * DMODEL / 4)      // 262144
#define SPLIT_BLOCKS ((N4X + 4 * N4W) / 256)

__global__ void split_all_kernel(const float4* __restrict__ x,
                                 const float4* __restrict__ Wq,
                                 const float4* __restrict__ Wk,
                                 const float4* __restrict__ Wv,
                                 const float4* __restrict__ Wo)
{
    int gi = blockIdx.x * 256 + threadIdx.x;
    const float4* src;
    __half2* dh;
    int i;
    if (gi < N4X) {
        src = x; i = gi;
        dh = reinterpret_cast<__half2*>(g_xh);
    } else {
        int wi = gi - N4X;
        int z = wi / N4W;
        i = wi - z * N4W;
        src = (z == 0) ? Wq : ((z == 1) ? Wk : ((z == 2) ? Wv : Wo));
        dh = reinterpret_cast<__half2*>(g_Wh + (size_t)z * DMODEL * DMODEL);
    }
    float4 v = src[i];
    dh[2 * i + 0] = __half2(__float2half_rn(v.x), __float2half_rn(v.y));
    dh[2 * i + 1] = __half2(__float2half_rn(v.z), __float2half_rn(v.w));
}

// ---------------- fp16 mma GEMM core (1-term) --------------------------------
#define BM 128
#define BN 128
#define CHUNKS 16
#define ATILE 16384
#define GEMM_STB (2 * ATILE)
#define GEMM_SMEM (3 * GEMM_STB)   // 96KB

// PROJ=0: z=blockIdx.z selects Q/K/V, writes [B,H,S,DK] scratch
// PROJ=1: output projection, writes fp32 out
template <int PROJ>
__global__ __launch_bounds__(256, 2) void mma_gemm(
    const float* __restrict__ b0, const float* __restrict__ b1,
    const float* __restrict__ b2, float* __restrict__ outp)
{
    extern __shared__ char smg[];
    const uint32_t sbase = smem_u32(smg);
    const int tid = threadIdx.x, wid = tid >> 5, lane = tid & 31;
    const int warp_m = wid & 3, warp_n = wid >> 2;
    const int m0 = blockIdx.x * BM;
    const int n0 = blockIdx.y * BN;
    const int z  = PROJ ? 3 : blockIdx.z;

    const __half* Ah = PROJ ? g_ah : g_xh;
    const __half* Bh = g_Wh + (size_t)z * DMODEL * DMODEL;
    const float* bias = PROJ ? b0 : ((z == 0) ? b0 : ((z == 1) ? b1 : b2));

    float cacc[2][8][4];
#pragma unroll
    for (int mi = 0; mi < 2; mi++)
#pragma unroll
        for (int ni = 0; ni < 8; ni++)
#pragma unroll
            for (int q = 0; q < 4; q++) cacc[mi][ni][q] = 0.f;

    auto load_chunk = [&](int c, int stage) {
        const int kk = c * 64;
        const uint32_t sA = sbase + (uint32_t)stage * GEMM_STB;
        const uint32_t sB = sA + ATILE;
#pragma unroll
        for (int i = 0; i < 4; i++) {
            int u = tid + i * 256;       // 0..1023
            int row = u >> 3, c16 = u & 7;
            uint32_t so = swz((uint32_t)(row * 128 + c16 * 16));
            size_t go = (size_t)row * DMODEL + kk + c16 * 8;
            cp16(sA + so, Ah + (size_t)m0 * DMODEL + go);
            cp16(sB + so, Bh + (size_t)n0 * DMODEL + go);
        }
    };

    load_chunk(0, 0); CP_COMMIT();
    load_chunk(1, 1); CP_COMMIT();

    for (int c = 0; c < CHUNKS; c++) {
        if (c + 1 < CHUNKS) CP_WAIT1(); else CP_WAIT0();
        __syncthreads();
        if (c + 2 < CHUNKS) { load_chunk(c + 2, (c + 2) % 3); CP_COMMIT(); }

        const uint32_t sA = sbase + (uint32_t)(c % 3) * GEMM_STB;
        const uint32_t sB = sA + ATILE;

#pragma unroll
        for (int ks = 0; ks < 4; ks++) {
            uint32_t ah[2][4], b[4][4];
#pragma unroll
            for (int mi = 0; mi < 2; mi++) {
                int r = warp_m * 32 + mi * 16 + (lane & 15);
                ldsm4(ah[mi], sA + swz((uint32_t)(r * 128 + ks * 32 + ((lane >> 4) << 4))));
            }
#pragma unroll
            for (int nb = 0; nb < 4; nb++) {
                int n = warp_n * 64 + nb * 16 + (lane & 7) + ((lane >> 4) << 3);
                ldsm4(b[nb], sB + swz((uint32_t)(n * 128 + ks * 32 + (((lane >> 3) & 1) << 4))));
            }
#pragma unroll
            for (int mi = 0; mi < 2; mi++)
#pragma unroll
                for (int ni = 0; ni < 8; ni++)
                    mma16816(cacc[mi][ni], ah[mi], &b[ni >> 1][(ni & 1) * 2]);
        }
    }

    const int row_base = m0 + warp_m * 32 + (lane >> 2);
    const int col_base = n0 + warp_n * 64 + (lane & 3) * 2;
#pragma unroll
    for (int ni = 0; ni < 8; ni++) {
        const int cc = col_base + ni * 8;
        const float bz0 = __ldg(&bias[cc]);
        const float bz1 = __ldg(&bias[cc + 1]);
#pragma unroll
        for (int mi = 0; mi < 2; mi++) {
#pragma unroll
            for (int half = 0; half < 2; half++) {
                const int m = row_base + mi * 16 + half * 8;
                float vx = cacc[mi][ni][half * 2 + 0] + bz0;
                float vy = cacc[mi][ni][half * 2 + 1] + bz1;
                if (PROJ) {
                    float2 v; v.x = vx; v.y = vy;
                    *reinterpret_cast<float2*>(&outp[(size_t)m * DMODEL + cc]) = v;
                } else {
                    const int bb = m >> 11, s = m & (SEQ - 1);
                    const int hd = cc >> 6, d = cc & 63;
                    size_t idx = (((size_t)(bb * NHEADS + hd)) * SEQ + s) * DK + d;
                    if (z == 0) { vx *= QSCALE; vy *= QSCALE; }
                    __half* dst = (z == 0) ? g_Qh : ((z == 1) ? g_Kh : g_Vh);
                    *reinterpret_cast<__half2*>(dst + idx) =
                        __half2(__float2half_rn(vx), __float2half_rn(vy));
                }
            }
        }
    }
}

// ---------------- tensor-core causal flash attention (fp16, 1-term) ---------
// 128 threads / 4 warps, Q tile 64 rows, KV tile 64, 2 KV stages of 16KB.
// Q parked inside stage 1 during prologue. 32KB smem -> 5 CTAs/SM.
#define ASTAGE_BYTES 16384
#define ATTN_SMEM    (2 * ASTAGE_BYTES)   // 32KB

__global__ __launch_bounds__(128, 5) void attn_mma_kernel()
{
    extern __shared__ char smem[];
    const uint32_t sb = smem_u32(smem);
    const int tid = threadIdx.x, wid = tid >> 5, lane = tid & 31;
    const int qi = gridDim.x - 1 - blockIdx.x;   // long tiles first
    const int bh = blockIdx.y;
    const int q0 = qi * 64;
    const size_t base = (size_t)bh * SEQ * DK;

    const int nkt = qi + 1;
    auto load_kv = [&](int kt) {
        uint32_t st = sb + (uint32_t)(kt & 1) * ASTAGE_BYTES;
        const size_t ko = base + (size_t)kt * 64 * DK;
#pragma unroll
        for (int i = 0; i < 4; i++) {
            int u = tid + i * 128;        // 0..511
            int row = u >> 3, c16 = u & 7;
            uint32_t so = swz((uint32_t)(row * 128 + c16 * 16));
            cp16(st + so,        g_Kh + ko + (size_t)row * DK + c16 * 8);
            cp16(st + 8192 + so, g_Vh + ko + (size_t)row * DK + c16 * 8);
        }
    };

    // Prologue: Qh parked in stage 1 (8KB), kv0 -> stage 0; one group.
    const uint32_t sQh = sb + ASTAGE_BYTES;
#pragma unroll
    for (int i = 0; i < 4; i++) {
        int u = tid + i * 128;            // 0..511
        int row = u >> 3, c16 = u & 7;
        uint32_t so = swz((uint32_t)(row * 128 + c16 * 16));
        cp16(sQh + so, g_Qh + base + (size_t)(q0 + row) * DK + c16 * 8);
    }
    load_kv(0);
    CP_COMMIT();
    CP_WAIT0();
    __syncthreads();

    uint32_t qh[4][4];
    {
        int r = wid * 16 + (lane & 15);
        uint32_t half = (uint32_t)((lane >> 4) << 4);
#pragma unroll
        for (int kc = 0; kc < 4; kc++)
            ldsm4(qh[kc], sQh + swz((uint32_t)(r * 128 + kc * 32) + half));
    }
    __syncthreads();   // Q reads done before stage 1 reloads

    const int nrow = (lane & 7) + ((lane >> 4) << 3);
    const uint32_t koff = (uint32_t)(((lane >> 3) & 1) << 4);
    const int vkey = ((lane >> 3) & 1) * 8 + (lane & 7);
    const uint32_t vdk = (uint32_t)(((lane >> 4) << 3) * 2);

    float o[8][4];
#pragma unroll
    for (int nt = 0; nt < 8; nt++)
#pragma unroll
        for (int q = 0; q < 4; q++) o[nt][q] = 0.f;
    float m0v = -3.0e38f, m1v = -3.0e38f, l0 = 0.f, l1 = 0.f;

    const int rq = q0 + wid * 16 + (lane >> 2);

    for (int kt = 0; kt < nkt; kt++) {
        if (kt > 0) {
            CP_WAIT0();          // kv(kt) landed
            __syncthreads();     // stage (kt+1)&1 fully consumed by all warps
        }
        if (kt + 1 < nkt) { load_kv(kt + 1); CP_COMMIT(); }

        const uint32_t st = sb + (uint32_t)(kt & 1) * ASTAGE_BYTES;

        // ---- S[64q x 64k] = Qh·Kh ----
        float s[8][4];
#pragma unroll
        for (int nt = 0; nt < 8; nt++)
#pragma unroll
            for (int q = 0; q < 4; q++) s[nt][q] = 0.f;

#pragma unroll
        for (int kc = 0; kc < 4; kc++) {
            uint32_t kb[16];
#pragma unroll
            for (int nb = 0; nb < 4; nb++)
                ldsm4(kb + nb * 4, st + swz((uint32_t)((nb * 16 + nrow) * 128 + kc * 32) + koff));
#pragma unroll
            for (int nt = 0; nt < 8; nt++) mma16816(s[nt], qh[kc], &kb[nt * 2]);
        }

        // ---- causal mask (diagonal tile only) ----
        if (kt == qi) {
            const int cb = kt * 64 + 2 * (lane & 3);
#pragma unroll
            for (int nt = 0; nt < 8; nt++) {
                int c0 = cb + 8 * nt;
                if (c0     > rq)     s[nt][0] = -1.0e30f;
                if (c0 + 1 > rq)     s[nt][1] = -1.0e30f;
                if (c0     > rq + 8) s[nt][2] = -1.0e30f;
                if (c0 + 1 > rq + 8) s[nt][3] = -1.0e30f;
            }
        }

        // ---- online softmax ----
        float mx0 = -3.0e38f, mx1 = -3.0e38f;
#pragma unroll
        for (int nt = 0; nt < 8; nt++) {
            mx0 = fmaxf(mx0, fmaxf(s[nt][0], s[nt][1]));
            mx1 = fmaxf(mx1, fmaxf(s[nt][2], s[nt][3]));
        }
        mx0 = fmaxf(mx0, __shfl_xor_sync(0xFFFFFFFFu, mx0, 1));
        mx0 = fmaxf(mx0, __shfl_xor_sync(0xFFFFFFFFu, mx0, 2));
        mx1 = fmaxf(mx1, __shfl_xor_sync(0xFFFFFFFFu, mx1, 1));
        mx1 = fmaxf(mx1, __shfl_xor_sync(0xFFFFFFFFu, mx1, 2));
        const float mn0 = fmaxf(m0v, mx0), mn1 = fmaxf(m1v, mx1);
        const float f0 = exp2f_fast(m0v - mn0), f1 = exp2f_fast(m1v - mn1);
        m0v = mn0; m1v = mn1;

        float sum0 = 0.f, sum1 = 0.f;
        uint32_t ph[4][4];
#pragma unroll
        for (int kc = 0; kc < 4; kc++) {
            float e00 = exp2f_fast(s[2*kc][0]   - mn0);
            float e01 = exp2f_fast(s[2*kc][1]   - mn0);
            float e10 = exp2f_fast(s[2*kc][2]   - mn1);
            float e11 = exp2f_fast(s[2*kc][3]   - mn1);
            float e20 = exp2f_fast(s[2*kc+1][0] - mn0);
            float e21 = exp2f_fast(s[2*kc+1][1] - mn0);
            float e30 = exp2f_fast(s[2*kc+1][2] - mn1);
            float e31 = exp2f_fast(s[2*kc+1][3] - mn1);
            sum0 += (e00 + e01) + (e20 + e21);
            sum1 += (e10 + e11) + (e30 + e31);
            ph[kc][0] = pack2(e00, e01);
            ph[kc][1] = pack2(e10, e11);
            ph[kc][2] = pack2(e20, e21);
            ph[kc][3] = pack2(e30, e31);
        }
        sum0 += __shfl_xor_sync(0xFFFFFFFFu, sum0, 1);
        sum0 += __shfl_xor_sync(0xFFFFFFFFu, sum0, 2);
        sum1 += __shfl_xor_sync(0xFFFFFFFFu, sum1, 1);
        sum1 += __shfl_xor_sync(0xFFFFFFFFu, sum1, 2);
        l0 = l0 * f0 + sum0;
        l1 = l1 * f1 + sum1;

#pragma unroll
        for (int nt = 0; nt < 8; nt++) {
            o[nt][0] *= f0; o[nt][1] *= f0;
            o[nt][2] *= f1; o[nt][3] *= f1;
        }

        // ---- O += Ph·Vh ----
        const uint32_t stv = st + 8192;
#pragma unroll
        for (int kc = 0; kc < 4; kc++) {
            uint32_t vb[16];
#pragma unroll
            for (int p4 = 0; p4 < 4; p4++)
                ldsm4t(vb + p4 * 4, stv +
                       swz((uint32_t)((kc * 16 + vkey) * 128 + p4 * 32) + vdk));
#pragma unroll
            for (int nt = 0; nt < 8; nt++) mma16816(o[nt], ph[kc], &vb[nt * 2]);
        }
    }

    // ---- epilogue: normalize, store fp16 hi to [B,S,H*DK] ----
    const float inv0 = 1.0f / l0, inv1 = 1.0f / l1;
    const int b = bh >> 4, hd = bh & 15;
    const int dkb = 2 * (lane & 3);
#pragma unroll
    for (int nt = 0; nt < 8; nt++) {
        const int d = hd * 64 + dkb + 8 * nt;
        size_t i0 = ((size_t)b * SEQ + rq) * DMODEL + d;
        size_t i1 = ((size_t)b * SEQ + rq + 8) * DMODEL + d;
        uint32_t p0 = pack2(o[nt][0] * inv0, o[nt][1] * inv0);
        uint32_t p1 = pack2(o[nt][2] * inv1, o[nt][3] * inv1);
        *reinterpret_cast<uint32_t*>(g_ah + i0) = p0;
        *reinterpret_cast<uint32_t*>(g_ah + i1) = p1;
    }
}

// ---------------------------------------------------------------------------
extern "C" void kernel_launch(void* const* d_in, const int* in_sizes, int n_in,
                              void* d_out, int out_size)
{
    const float* x  = (const float*)d_in[0];
    const float* Wq = (const float*)d_in[1];
    const float* bq = (const float*)d_in[2];
    const float* Wk = (const float*)d_in[3];
    const float* bk = (const float*)d_in[4];
    const float* Wv = (const float*)d_in[5];
    const float* bv = (const float*)d_in[6];
    const float* Wo = (const float*)d_in[7];
    const float* bo = (const float*)d_in[8];
    float* out = (float*)d_out;
    (void)in_sizes; (void)n_in; (void)out_size;

    static bool attr_done = false;
    if (!attr_done) {
        cudaFuncSetAttribute(mma_gemm<0>, cudaFuncAttributeMaxDynamicSharedMemorySize, GEMM_SMEM);
        cudaFuncSetAttribute(mma_gemm<1>, cudaFuncAttributeMaxDynamicSharedMemorySize, GEMM_SMEM);
        cudaFuncSetAttribute(attn_mma_kernel, cudaFuncAttributeMaxDynamicSharedMemorySize, ATTN_SMEM);
        attr_done = true;
    }

    split_all_kernel<<<SPLIT_BLOCKS, 256>>>((const float4*)x, (const float4*)Wq,
                                            (const float4*)Wk, (const float4*)Wv,
                                            (const float4*)Wo);

    dim3 gQKV(MTOT / BM, DMODEL / BN, 3);
    mma_gemm<0><<<gQKV, 256, GEMM_SMEM>>>(bq, bk, bv, nullptr);

    dim3 gAttn(SEQ / 64, BATCH * NHEADS);
    attn_mma_kernel<<<gAttn, 128, ATTN_SMEM>>>();

    dim3 gProj(MTOT / BM, DMODEL / BN);
    mma_gemm<1><<<gProj, 256, GEMM_SMEM>>>(bo, nullptr, nullptr, out);
}

// round 15
// speedup vs baseline: 1.3931x; 1.0038x over previous
#include <cuda_runtime.h>
#include <cuda_fp16.h>
#include <cstdint>
#include <math.h>

#define DMODEL 1024
#define NHEADS 16
#define DK     64
#define BATCH  4
#define SEQ    2048
#define MTOT   (BATCH*SEQ)   // 8192

#define QSCALE 0.1803368801111204f   // 0.125 * log2(e)

// ---------------- device scratch (allocation-free) ----------------
__device__ __half g_Qh[(size_t)MTOT * DMODEL];  // [B*H][S][DK]
__device__ __half g_Kh[(size_t)MTOT * DMODEL];
__device__ __half g_Vh[(size_t)MTOT * DMODEL];
__device__ __half g_xh[(size_t)MTOT * DMODEL];
__device__ __half g_Wh[(size_t)4 * DMODEL * DMODEL];
__device__ __half g_ah[(size_t)MTOT * DMODEL];  // attn out [B,S,H*DK]

// ---------------- helpers ----------------
__device__ __forceinline__ uint32_t smem_u32(const void* p) {
    uint32_t a;
    asm("{ .reg .u64 t; cvta.to.shared.u64 t, %1; cvt.u32.u64 %0, t; }" : "=r"(a) : "l"(p));
    return a;
}
__device__ __forceinline__ uint32_t swz(uint32_t o) { return o ^ ((o >> 3) & 0x70); }

__device__ __forceinline__ void cp16(uint32_t dst, const void* src) {
    asm volatile("cp.async.cg.shared.global [%0], [%1], 16;" :: "r"(dst), "l"(src));
}
#define CP_COMMIT() asm volatile("cp.async.commit_group;" ::: "memory")
#define CP_WAIT0()  asm volatile("cp.async.wait_group 0;" ::: "memory")
#define CP_WAIT1()  asm volatile("cp.async.wait_group 1;" ::: "memory")

__device__ __forceinline__ void ldsm4(uint32_t* r, uint32_t a) {
    asm volatile("ldmatrix.sync.aligned.m8n8.x4.shared.b16 {%0,%1,%2,%3}, [%4];"
                 : "=r"(r[0]), "=r"(r[1]), "=r"(r[2]), "=r"(r[3]) : "r"(a));
}
__device__ __forceinline__ void ldsm4t(uint32_t* r, uint32_t a) {
    asm volatile("ldmatrix.sync.aligned.m8n8.x4.trans.shared.b16 {%0,%1,%2,%3}, [%4];"
                 : "=r"(r[0]), "=r"(r[1]), "=r"(r[2]), "=r"(r[3]) : "r"(a));
}
__device__ __forceinline__ void mma16816(float* c, const uint32_t* a, const uint32_t* b) {
    asm volatile("mma.sync.aligned.m16n8k16.row.col.f32.f16.f16.f32 "
                 "{%0,%1,%2,%3}, {%4,%5,%6,%7}, {%8,%9}, {%0,%1,%2,%3};"
                 : "+f"(c[0]), "+f"(c[1]), "+f"(c[2]), "+f"(c[3])
                 : "r"(a[0]), "r"(a[1]), "r"(a[2]), "r"(a[3]), "r"(b[0]), "r"(b[1]));
}

// Fast exp2 for t <= 0 (FMA pipe; err ~4e-5 rel)
__device__ __forceinline__ float exp2f_fast(float t) {
    t = fmaxf(t, -80.0f);
    float a = __fadd_rn(t, 12582912.0f);
    float r = __fsub_rn(t, __fsub_rn(a, 12582912.0f));
    float p = fmaf(r, 0.0096181291f, 0.0555041087f);
    p = fmaf(p, r, 0.2402265069f);
    p = fmaf(p, r, 0.6931471806f);
    p = fmaf(p, r, 1.0f);
    return __int_as_float(__float_as_int(p) + (__float_as_int(a) << 23));
}

__device__ __forceinline__ uint32_t pack2(float x, float y) {
    __half2 h = __floats2half2_rn(x, y);
    return *reinterpret_cast<uint32_t*>(&h);
}

// ---------------- fused split: x, Wq/Wk/Wv/Wo -> fp16 (vectorized) ----------
// Each thread: 2 float4 in (32B) -> 1 uint4 out (16B).
#define N8X (MTOT * DMODEL / 8)        // 1048576
#define N8W (DMODEL * DMODEL / 8)      // 131072
#define SPLIT_BLOCKS ((N8X + 4 * N8W) / 256)

__global__ void split_all_kernel(const float4* __restrict__ x,
                                 const float4* __restrict__ Wq,
                                 const float4* __restrict__ Wk,
                                 const float4* __restrict__ Wv,
                                 const float4* __restrict__ Wo)
{
    int gi = blockIdx.x * 256 + threadIdx.x;
    const float4* src;
    uint4* dh;
    int i;
    if (gi < N8X) {
        src = x; i = gi;
        dh = reinterpret_cast<uint4*>(g_xh);
    } else {
        int wi = gi - N8X;
        int z = wi / N8W;
        i = wi - z * N8W;
        src = (z == 0) ? Wq : ((z == 1) ? Wk : ((z == 2) ? Wv : Wo));
        dh = reinterpret_cast<uint4*>(g_Wh + (size_t)z * DMODEL * DMODEL);
    }
    float4 a = src[2 * i];
    float4 b = src[2 * i + 1];
    uint4 o;
    o.x = pack2(a.x, a.y);
    o.y = pack2(a.z, a.w);
    o.z = pack2(b.x, b.y);
    o.w = pack2(b.z, b.w);
    dh[i] = o;
}

// ---------------- fp16 mma GEMM core (1-term) --------------------------------
#define BM 128
#define BN 128
#define CHUNKS 16
#define ATILE 16384
#define GEMM_STB (2 * ATILE)
#define GEMM_SMEM (3 * GEMM_STB)   // 96KB

// PROJ=0: z=blockIdx.z selects Q/K/V, writes [B,H,S,DK] scratch
// PROJ=1: output projection, writes fp32 out
template <int PROJ>
__global__ __launch_bounds__(256, 2) void mma_gemm(
    const float* __restrict__ b0, const float* __restrict__ b1,
    const float* __restrict__ b2, float* __restrict__ outp)
{
    extern __shared__ char smg[];
    const uint32_t sbase = smem_u32(smg);
    const int tid = threadIdx.x, wid = tid >> 5, lane = tid & 31;
    const int warp_m = wid & 3, warp_n = wid >> 2;
    const int m0 = blockIdx.x * BM;
    const int n0 = blockIdx.y * BN;
    const int z  = PROJ ? 3 : blockIdx.z;

    const __half* Ah = PROJ ? g_ah : g_xh;
    const __half* Bh = g_Wh + (size_t)z * DMODEL * DMODEL;
    const float* bias = PROJ ? b0 : ((z == 0) ? b0 : ((z == 1) ? b1 : b2));

    float cacc[2][8][4];
#pragma unroll
    for (int mi = 0; mi < 2; mi++)
#pragma unroll
        for (int ni = 0; ni < 8; ni++)
#pragma unroll
            for (int q = 0; q < 4; q++) cacc[mi][ni][q] = 0.f;

    auto load_chunk = [&](int c, int stage) {
        const int kk = c * 64;
        const uint32_t sA = sbase + (uint32_t)stage * GEMM_STB;
        const uint32_t sB = sA + ATILE;
#pragma unroll
        for (int i = 0; i < 4; i++) {
            int u = tid + i * 256;       // 0..1023
            int row = u >> 3, c16 = u & 7;
            uint32_t so = swz((uint32_t)(row * 128 + c16 * 16));
            size_t go = (size_t)row * DMODEL + kk + c16 * 8;
            cp16(sA + so, Ah + (size_t)m0 * DMODEL + go);
            cp16(sB + so, Bh + (size_t)n0 * DMODEL + go);
        }
    };

    load_chunk(0, 0); CP_COMMIT();
    load_chunk(1, 1); CP_COMMIT();

    for (int c = 0; c < CHUNKS; c++) {
        if (c + 1 < CHUNKS) CP_WAIT1(); else CP_WAIT0();
        __syncthreads();
        if (c + 2 < CHUNKS) { load_chunk(c + 2, (c + 2) % 3); CP_COMMIT(); }

        const uint32_t sA = sbase + (uint32_t)(c % 3) * GEMM_STB;
        const uint32_t sB = sA + ATILE;

#pragma unroll
        for (int ks = 0; ks < 4; ks++) {
            uint32_t ah[2][4], b[4][4];
#pragma unroll
            for (int mi = 0; mi < 2; mi++) {
                int r = warp_m * 32 + mi * 16 + (lane & 15);
                ldsm4(ah[mi], sA + swz((uint32_t)(r * 128 + ks * 32 + ((lane >> 4) << 4))));
            }
#pragma unroll
            for (int nb = 0; nb < 4; nb++) {
                int n = warp_n * 64 + nb * 16 + (lane & 7) + ((lane >> 4) << 3);
                ldsm4(b[nb], sB + swz((uint32_t)(n * 128 + ks * 32 + (((lane >> 3) & 1) << 4))));
            }
#pragma unroll
            for (int mi = 0; mi < 2; mi++)
#pragma unroll
                for (int ni = 0; ni < 8; ni++)
                    mma16816(cacc[mi][ni], ah[mi], &b[ni >> 1][(ni & 1) * 2]);
        }
    }

    const int row_base = m0 + warp_m * 32 + (lane >> 2);
    const int col_base = n0 + warp_n * 64 + (lane & 3) * 2;
#pragma unroll
    for (int ni = 0; ni < 8; ni++) {
        const int cc = col_base + ni * 8;
        const float bz0 = __ldg(&bias[cc]);
        const float bz1 = __ldg(&bias[cc + 1]);
#pragma unroll
        for (int mi = 0; mi < 2; mi++) {
#pragma unroll
            for (int half = 0; half < 2; half++) {
                const int m = row_base + mi * 16 + half * 8;
                float vx = cacc[mi][ni][half * 2 + 0] + bz0;
                float vy = cacc[mi][ni][half * 2 + 1] + bz1;
                if (PROJ) {
                    float2 v; v.x = vx; v.y = vy;
                    *reinterpret_cast<float2*>(&outp[(size_t)m * DMODEL + cc]) = v;
                } else {
                    const int bb = m >> 11, s = m & (SEQ - 1);
                    const int hd = cc >> 6, d = cc & 63;
                    size_t idx = (((size_t)(bb * NHEADS + hd)) * SEQ + s) * DK + d;
                    if (z == 0) { vx *= QSCALE; vy *= QSCALE; }
                    __half* dst = (z == 0) ? g_Qh : ((z == 1) ? g_Kh : g_Vh);
                    *reinterpret_cast<__half2*>(dst + idx) =
                        __half2(__float2half_rn(vx), __float2half_rn(vy));
                }
            }
        }
    }
}

// ---------------- tensor-core causal flash attention (fp16, 1-term) ---------
// 128 threads / 4 warps, Q tile 64 rows, KV tile 64, 2 KV stages of 16KB.
// Q parked inside stage 1 during prologue. 32KB smem -> 5 CTAs/SM.
#define ASTAGE_BYTES 16384
#define ATTN_SMEM    (2 * ASTAGE_BYTES)   // 32KB

__global__ __launch_bounds__(128, 5) void attn_mma_kernel()
{
    extern __shared__ char smem[];
    const uint32_t sb = smem_u32(smem);
    const int tid = threadIdx.x, wid = tid >> 5, lane = tid & 31;
    const int qi = gridDim.x - 1 - blockIdx.x;   // long tiles first
    const int bh = blockIdx.y;
    const int q0 = qi * 64;
    const size_t base = (size_t)bh * SEQ * DK;

    const int nkt = qi + 1;
    auto load_kv = [&](int kt) {
        uint32_t st = sb + (uint32_t)(kt & 1) * ASTAGE_BYTES;
        const size_t ko = base + (size_t)kt * 64 * DK;
#pragma unroll
        for (int i = 0; i < 4; i++) {
            int u = tid + i * 128;        // 0..511
            int row = u >> 3, c16 = u & 7;
            uint32_t so = swz((uint32_t)(row * 128 + c16 * 16));
            cp16(st + so,        g_Kh + ko + (size_t)row * DK + c16 * 8);
            cp16(st + 8192 + so, g_Vh + ko + (size_t)row * DK + c16 * 8);
        }
    };

    // Prologue: Qh parked in stage 1 (8KB), kv0 -> stage 0; one group.
    const uint32_t sQh = sb + ASTAGE_BYTES;
#pragma unroll
    for (int i = 0; i < 4; i++) {
        int u = tid + i * 128;            // 0..511
        int row = u >> 3, c16 = u & 7;
        uint32_t so = swz((uint32_t)(row * 128 + c16 * 16));
        cp16(sQh + so, g_Qh + base + (size_t)(q0 + row) * DK + c16 * 8);
    }
    load_kv(0);
    CP_COMMIT();
    CP_WAIT0();
    __syncthreads();

    uint32_t qh[4][4];
    {
        int r = wid * 16 + (lane & 15);
        uint32_t half = (uint32_t)((lane >> 4) << 4);
#pragma unroll
        for (int kc = 0; kc < 4; kc++)
            ldsm4(qh[kc], sQh + swz((uint32_t)(r * 128 + kc * 32) + half));
    }
    __syncthreads();   // Q reads done before stage 1 reloads

    const int nrow = (lane & 7) + ((lane >> 4) << 3);
    const uint32_t koff = (uint32_t)(((lane >> 3) & 1) << 4);
    const int vkey = ((lane >> 3) & 1) * 8 + (lane & 7);
    const uint32_t vdk = (uint32_t)(((lane >> 4) << 3) * 2);

    float o[8][4];
#pragma unroll
    for (int nt = 0; nt < 8; nt++)
#pragma unroll
        for (int q = 0; q < 4; q++) o[nt][q] = 0.f;
    float m0v = -3.0e38f, m1v = -3.0e38f, l0 = 0.f, l1 = 0.f;

    const int rq = q0 + wid * 16 + (lane >> 2);

    for (int kt = 0; kt < nkt; kt++) {
        if (kt > 0) {
            CP_WAIT0();          // kv(kt) landed
            __syncthreads();     // stage (kt+1)&1 fully consumed by all warps
        }
        if (kt + 1 < nkt) { load_kv(kt + 1); CP_COMMIT(); }

        const uint32_t st = sb + (uint32_t)(kt & 1) * ASTAGE_BYTES;

        // ---- S[64q x 64k] = Qh·Kh ----
        float s[8][4];
#pragma unroll
        for (int nt = 0; nt < 8; nt++)
#pragma unroll
            for (int q = 0; q < 4; q++) s[nt][q] = 0.f;

#pragma unroll
        for (int kc = 0; kc < 4; kc++) {
            uint32_t kb[16];
#pragma unroll
            for (int nb = 0; nb < 4; nb++)
                ldsm4(kb + nb * 4, st + swz((uint32_t)((nb * 16 + nrow) * 128 + kc * 32) + koff));
#pragma unroll
            for (int nt = 0; nt < 8; nt++) mma16816(s[nt], qh[kc], &kb[nt * 2]);
        }

        // ---- causal mask (diagonal tile only) ----
        if (kt == qi) {
            const int cb = kt * 64 + 2 * (lane & 3);
#pragma unroll
            for (int nt = 0; nt < 8; nt++) {
                int c0 = cb + 8 * nt;
                if (c0     > rq)     s[nt][0] = -1.0e30f;
                if (c0 + 1 > rq)     s[nt][1] = -1.0e30f;
                if (c0     > rq + 8) s[nt][2] = -1.0e30f;
                if (c0 + 1 > rq + 8) s[nt][3] = -1.0e30f;
            }
        }

        // ---- online softmax ----
        float mx0 = -3.0e38f, mx1 = -3.0e38f;
#pragma unroll
        for (int nt = 0; nt < 8; nt++) {
            mx0 = fmaxf(mx0, fmaxf(s[nt][0], s[nt][1]));
            mx1 = fmaxf(mx1, fmaxf(s[nt][2], s[nt][3]));
        }
        mx0 = fmaxf(mx0, __shfl_xor_sync(0xFFFFFFFFu, mx0, 1));
        mx0 = fmaxf(mx0, __shfl_xor_sync(0xFFFFFFFFu, mx0, 2));
        mx1 = fmaxf(mx1, __shfl_xor_sync(0xFFFFFFFFu, mx1, 1));
        mx1 = fmaxf(mx1, __shfl_xor_sync(0xFFFFFFFFu, mx1, 2));
        const float mn0 = fmaxf(m0v, mx0), mn1 = fmaxf(m1v, mx1);
        const float f0 = exp2f_fast(m0v - mn0), f1 = exp2f_fast(m1v - mn1);
        m0v = mn0; m1v = mn1;

        float sum0 = 0.f, sum1 = 0.f;
        uint32_t ph[4][4];
#pragma unroll
        for (int kc = 0; kc < 4; kc++) {
            float e00 = exp2f_fast(s[2*kc][0]   - mn0);
            float e01 = exp2f_fast(s[2*kc][1]   - mn0);
            float e10 = exp2f_fast(s[2*kc][2]   - mn1);
            float e11 = exp2f_fast(s[2*kc][3]   - mn1);
            float e20 = exp2f_fast(s[2*kc+1][0] - mn0);
            float e21 = exp2f_fast(s[2*kc+1][1] - mn0);
            float e30 = exp2f_fast(s[2*kc+1][2] - mn1);
            float e31 = exp2f_fast(s[2*kc+1][3] - mn1);
            sum0 += (e00 + e01) + (e20 + e21);
            sum1 += (e10 + e11) + (e30 + e31);
            ph[kc][0] = pack2(e00, e01);
            ph[kc][1] = pack2(e10, e11);
            ph[kc][2] = pack2(e20, e21);
            ph[kc][3] = pack2(e30, e31);
        }
        sum0 += __shfl_xor_sync(0xFFFFFFFFu, sum0, 1);
        sum0 += __shfl_xor_sync(0xFFFFFFFFu, sum0, 2);
        sum1 += __shfl_xor_sync(0xFFFFFFFFu, sum1, 1);
        sum1 += __shfl_xor_sync(0xFFFFFFFFu, sum1, 2);
        l0 = l0 * f0 + sum0;
        l1 = l1 * f1 + sum1;

#pragma unroll
        for (int nt = 0; nt < 8; nt++) {
            o[nt][0] *= f0; o[nt][1] *= f0;
            o[nt][2] *= f1; o[nt][3] *= f1;
        }

        // ---- O += Ph·Vh ----
        const uint32_t stv = st + 8192;
#pragma unroll
        for (int kc = 0; kc < 4; kc++) {
            uint32_t vb[16];
#pragma unroll
            for (int p4 = 0; p4 < 4; p4++)
                ldsm4t(vb + p4 * 4, stv +
                       swz((uint32_t)((kc * 16 + vkey) * 128 + p4 * 32) + vdk));
#pragma unroll
            for (int nt = 0; nt < 8; nt++) mma16816(o[nt], ph[kc], &vb[nt * 2]);
        }
    }

    // ---- epilogue: normalize, store fp16 hi to [B,S,H*DK] ----
    const float inv0 = 1.0f / l0, inv1 = 1.0f / l1;
    const int b = bh >> 4, hd = bh & 15;
    const int dkb = 2 * (lane & 3);
#pragma unroll
    for (int nt = 0; nt < 8; nt++) {
        const int d = hd * 64 + dkb + 8 * nt;
        size_t i0 = ((size_t)b * SEQ + rq) * DMODEL + d;
        size_t i1 = ((size_t)b * SEQ + rq + 8) * DMODEL + d;
        uint32_t p0 = pack2(o[nt][0] * inv0, o[nt][1] * inv0);
        uint32_t p1 = pack2(o[nt][2] * inv1, o[nt][3] * inv1);
        *reinterpret_cast<uint32_t*>(g_ah + i0) = p0;
        *reinterpret_cast<uint32_t*>(g_ah + i1) = p1;
    }
}

// ---------------------------------------------------------------------------
extern "C" void kernel_launch(void* const* d_in, const int* in_sizes, int n_in,
                              void* d_out, int out_size)
{
    const float* x  = (const float*)d_in[0];
    const float* Wq = (const float*)d_in[1];
    const float* bq = (const float*)d_in[2];
    const float* Wk = (const float*)d_in[3];
    const float* bk = (const float*)d_in[4];
    const float* Wv = (const float*)d_in[5];
    const float* bv = (const float*)d_in[6];
    const float* Wo = (const float*)d_in[7];
    const float* bo = (const float*)d_in[8];
    float* out = (float*)d_out;
    (void)in_sizes; (void)n_in; (void)out_size;

    static bool attr_done = false;
    if (!attr_done) {
        cudaFuncSetAttribute(mma_gemm<0>, cudaFuncAttributeMaxDynamicSharedMemorySize, GEMM_SMEM);
        cudaFuncSetAttribute(mma_gemm<1>, cudaFuncAttributeMaxDynamicSharedMemorySize, GEMM_SMEM);
        cudaFuncSetAttribute(attn_mma_kernel, cudaFuncAttributeMaxDynamicSharedMemorySize, ATTN_SMEM);
        attr_done = true;
    }

    split_all_kernel<<<SPLIT_BLOCKS, 256>>>((const float4*)x, (const float4*)Wq,
                                            (const float4*)Wk, (const float4*)Wv,
                                            (const float4*)Wo);

    dim3 gQKV(MTOT / BM, DMODEL / BN, 3);
    mma_gemm<0><<<gQKV, 256, GEMM_SMEM>>>(bq, bk, bv, nullptr);

    dim3 gAttn(SEQ / 64, BATCH * NHEADS);
    attn_mma_kernel<<<gAttn, 128, ATTN_SMEM>>>();

    dim3 gProj(MTOT / BM, DMODEL / BN);
    mma_gemm<1><<<gProj, 256, GEMM_SMEM>>>(bo, nullptr, nullptr, out);
}

// round 16
// speedup vs baseline: 1.4645x; 1.0512x over previous
#include <cuda_runtime.h>
#include <cuda_fp16.h>
#include <cstdint>
#include <math.h>

#define DMODEL 1024
#define NHEADS 16
#define DK     64
#define BATCH  4
#define SEQ    2048
#define MTOT   (BATCH*SEQ)   // 8192
#define NQT    (SEQ / 64)    // 32 q-tiles

#define QSCALE 0.1803368801111204f   // 0.125 * log2(e)

// ---------------- device scratch (allocation-free) ----------------
__device__ __half g_Qh[(size_t)MTOT * DMODEL];  // [B*H][S][DK]
__device__ __half g_Kh[(size_t)MTOT * DMODEL];
__device__ __half g_Vh[(size_t)MTOT * DMODEL];
__device__ __half g_xh[(size_t)MTOT * DMODEL];
__device__ __half g_Wh[(size_t)4 * DMODEL * DMODEL];
__device__ __half g_ah[(size_t)MTOT * DMODEL];  // attn out [B,S,H*DK]

// ---------------- helpers ----------------
__device__ __forceinline__ uint32_t smem_u32(const void* p) {
    uint32_t a;
    asm("{ .reg .u64 t; cvta.to.shared.u64 t, %1; cvt.u32.u64 %0, t; }" : "=r"(a) : "l"(p));
    return a;
}
__device__ __forceinline__ uint32_t swz(uint32_t o) { return o ^ ((o >> 3) & 0x70); }

__device__ __forceinline__ void cp16(uint32_t dst, const void* src) {
    asm volatile("cp.async.cg.shared.global [%0], [%1], 16;" :: "r"(dst), "l"(src));
}
#define CP_COMMIT() asm volatile("cp.async.commit_group;" ::: "memory")
#define CP_WAIT0()  asm volatile("cp.async.wait_group 0;" ::: "memory")
#define CP_WAIT1()  asm volatile("cp.async.wait_group 1;" ::: "memory")

__device__ __forceinline__ void ldsm4(uint32_t* r, uint32_t a) {
    asm volatile("ldmatrix.sync.aligned.m8n8.x4.shared.b16 {%0,%1,%2,%3}, [%4];"
                 : "=r"(r[0]), "=r"(r[1]), "=r"(r[2]), "=r"(r[3]) : "r"(a));
}
__device__ __forceinline__ void ldsm4t(uint32_t* r, uint32_t a) {
    asm volatile("ldmatrix.sync.aligned.m8n8.x4.trans.shared.b16 {%0,%1,%2,%3}, [%4];"
                 : "=r"(r[0]), "=r"(r[1]), "=r"(r[2]), "=r"(r[3]) : "r"(a));
}
__device__ __forceinline__ void mma16816(float* c, const uint32_t* a, const uint32_t* b) {
    asm volatile("mma.sync.aligned.m16n8k16.row.col.f32.f16.f16.f32 "
                 "{%0,%1,%2,%3}, {%4,%5,%6,%7}, {%8,%9}, {%0,%1,%2,%3};"
                 : "+f"(c[0]), "+f"(c[1]), "+f"(c[2]), "+f"(c[3])
                 : "r"(a[0]), "r"(a[1]), "r"(a[2]), "r"(a[3]), "r"(b[0]), "r"(b[1]));
}

// Fast exp2 for t <= 0 (FMA pipe; err ~4e-5 rel)
__device__ __forceinline__ float exp2f_fast(float t) {
    t = fmaxf(t, -80.0f);
    float a = __fadd_rn(t, 12582912.0f);
    float r = __fsub_rn(t, __fsub_rn(a, 12582912.0f));
    float p = fmaf(r, 0.0096181291f, 0.0555041087f);
    p = fmaf(p, r, 0.2402265069f);
    p = fmaf(p, r, 0.6931471806f);
    p = fmaf(p, r, 1.0f);
    return __int_as_float(__float_as_int(p) + (__float_as_int(a) << 23));
}

__device__ __forceinline__ uint32_t pack2(float x, float y) {
    __half2 h = __floats2half2_rn(x, y);
    return *reinterpret_cast<uint32_t*>(&h);
}

// ---------------- fused split: x, Wq/Wk/Wv/Wo -> fp16 (vectorized) ----------
#define N8X (MTOT * DMODEL / 8)        // 1048576
#define N8W (DMODEL * DMODEL / 8)      // 131072
#define SPLIT_BLOCKS ((N8X + 4 * N8W) / 256)

__global__ void split_all_kernel(const float4* __restrict__ x,
                                 const float4* __restrict__ Wq,
                                 const float4* __restrict__ Wk,
                                 const float4* __restrict__ Wv,
                                 const float4* __restrict__ Wo)
{
    int gi = blockIdx.x * 256 + threadIdx.x;
    const float4* src;
    uint4* dh;
    int i;
    if (gi < N8X) {
        src = x; i = gi;
        dh = reinterpret_cast<uint4*>(g_xh);
    } else {
        int wi = gi - N8X;
        int z = wi / N8W;
        i = wi - z * N8W;
        src = (z == 0) ? Wq : ((z == 1) ? Wk : ((z == 2) ? Wv : Wo));
        dh = reinterpret_cast<uint4*>(g_Wh + (size_t)z * DMODEL * DMODEL);
    }
    float4 a = src[2 * i];
    float4 b = src[2 * i + 1];
    uint4 o;
    o.x = pack2(a.x, a.y);
    o.y = pack2(a.z, a.w);
    o.z = pack2(b.x, b.y);
    o.w = pack2(b.z, b.w);
    dh[i] = o;
}

// ---------------- fp16 mma GEMM core (1-term) --------------------------------
#define BM 128
#define BN 128
#define CHUNKS 16
#define ATILE 16384
#define GEMM_STB (2 * ATILE)
#define GEMM_SMEM (3 * GEMM_STB)   // 96KB

template <int PROJ>
__global__ __launch_bounds__(256, 2) void mma_gemm(
    const float* __restrict__ b0, const float* __restrict__ b1,
    const float* __restrict__ b2, float* __restrict__ outp)
{
    extern __shared__ char smg[];
    const uint32_t sbase = smem_u32(smg);
    const int tid = threadIdx.x, wid = tid >> 5, lane = tid & 31;
    const int warp_m = wid & 3, warp_n = wid >> 2;
    const int m0 = blockIdx.x * BM;
    const int n0 = blockIdx.y * BN;
    const int z  = PROJ ? 3 : blockIdx.z;

    const __half* Ah = PROJ ? g_ah : g_xh;
    const __half* Bh = g_Wh + (size_t)z * DMODEL * DMODEL;
    const float* bias = PROJ ? b0 : ((z == 0) ? b0 : ((z == 1) ? b1 : b2));

    float cacc[2][8][4];
#pragma unroll
    for (int mi = 0; mi < 2; mi++)
#pragma unroll
        for (int ni = 0; ni < 8; ni++)
#pragma unroll
            for (int q = 0; q < 4; q++) cacc[mi][ni][q] = 0.f;

    auto load_chunk = [&](int c, int stage) {
        const int kk = c * 64;
        const uint32_t sA = sbase + (uint32_t)stage * GEMM_STB;
        const uint32_t sB = sA + ATILE;
#pragma unroll
        for (int i = 0; i < 4; i++) {
            int u = tid + i * 256;       // 0..1023
            int row = u >> 3, c16 = u & 7;
            uint32_t so = swz((uint32_t)(row * 128 + c16 * 16));
            size_t go = (size_t)row * DMODEL + kk + c16 * 8;
            cp16(sA + so, Ah + (size_t)m0 * DMODEL + go);
            cp16(sB + so, Bh + (size_t)n0 * DMODEL + go);
        }
    };

    load_chunk(0, 0); CP_COMMIT();
    load_chunk(1, 1); CP_COMMIT();

    for (int c = 0; c < CHUNKS; c++) {
        if (c + 1 < CHUNKS) CP_WAIT1(); else CP_WAIT0();
        __syncthreads();
        if (c + 2 < CHUNKS) { load_chunk(c + 2, (c + 2) % 3); CP_COMMIT(); }

        const uint32_t sA = sbase + (uint32_t)(c % 3) * GEMM_STB;
        const uint32_t sB = sA + ATILE;

#pragma unroll
        for (int ks = 0; ks < 4; ks++) {
            uint32_t ah[2][4], b[4][4];
#pragma unroll
            for (int mi = 0; mi < 2; mi++) {
                int r = warp_m * 32 + mi * 16 + (lane & 15);
                ldsm4(ah[mi], sA + swz((uint32_t)(r * 128 + ks * 32 + ((lane >> 4) << 4))));
            }
#pragma unroll
            for (int nb = 0; nb < 4; nb++) {
                int n = warp_n * 64 + nb * 16 + (lane & 7) + ((lane >> 4) << 3);
                ldsm4(b[nb], sB + swz((uint32_t)(n * 128 + ks * 32 + (((lane >> 3) & 1) << 4))));
            }
#pragma unroll
            for (int mi = 0; mi < 2; mi++)
#pragma unroll
                for (int ni = 0; ni < 8; ni++)
                    mma16816(cacc[mi][ni], ah[mi], &b[ni >> 1][(ni & 1) * 2]);
        }
    }

    const int row_base = m0 + warp_m * 32 + (lane >> 2);
    const int col_base = n0 + warp_n * 64 + (lane & 3) * 2;
#pragma unroll
    for (int ni = 0; ni < 8; ni++) {
        const int cc = col_base + ni * 8;
        const float bz0 = __ldg(&bias[cc]);
        const float bz1 = __ldg(&bias[cc + 1]);
#pragma unroll
        for (int mi = 0; mi < 2; mi++) {
#pragma unroll
            for (int half = 0; half < 2; half++) {
                const int m = row_base + mi * 16 + half * 8;
                float vx = cacc[mi][ni][half * 2 + 0] + bz0;
                float vy = cacc[mi][ni][half * 2 + 1] + bz1;
                if (PROJ) {
                    float2 v; v.x = vx; v.y = vy;
                    *reinterpret_cast<float2*>(&outp[(size_t)m * DMODEL + cc]) = v;
                } else {
                    const int bb = m >> 11, s = m & (SEQ - 1);
                    const int hd = cc >> 6, d = cc & 63;
                    size_t idx = (((size_t)(bb * NHEADS + hd)) * SEQ + s) * DK + d;
                    if (z == 0) { vx *= QSCALE; vy *= QSCALE; }
                    __half* dst = (z == 0) ? g_Qh : ((z == 1) ? g_Kh : g_Vh);
                    *reinterpret_cast<__half2*>(dst + idx) =
                        __half2(__float2half_rn(vx), __float2half_rn(vy));
                }
            }
        }
    }
}

// ---------------- tensor-core causal flash attention (fp16, 1-term) ---------
// 128 threads / 4 warps, Q tile 64 rows, KV tile 64, 2 KV stages of 16KB.
// Each CTA processes TWO complementary q-tiles (qi=x and qi=31-x) so every
// CTA does exactly 33 k-tile iterations -> perfectly balanced 1.4-wave grid.
// 32KB smem -> 5 CTAs/SM.
#define ASTAGE_BYTES 16384
#define ATTN_SMEM    (2 * ASTAGE_BYTES)   // 32KB

__global__ __launch_bounds__(128, 5) void attn_mma_kernel()
{
    extern __shared__ char smem[];
    const uint32_t sb = smem_u32(smem);
    const int tid = threadIdx.x, wid = tid >> 5, lane = tid & 31;
    const int bh = blockIdx.y;
    const size_t base = (size_t)bh * SEQ * DK;
    const int b = bh >> 4, hd = bh & 15;

    const int nrow = (lane & 7) + ((lane >> 4) << 3);
    const uint32_t koff = (uint32_t)(((lane >> 3) & 1) << 4);
    const int vkey = ((lane >> 3) & 1) * 8 + (lane & 7);
    const uint32_t vdk = (uint32_t)(((lane >> 4) << 3) * 2);
    const int dkb = 2 * (lane & 3);

#pragma unroll 1
    for (int part = 0; part < 2; part++) {
        const int qi = part ? (NQT - 1 - blockIdx.x) : blockIdx.x;
        const int q0 = qi * 64;
        const int nkt = qi + 1;

        auto load_kv = [&](int kt) {
            uint32_t st = sb + (uint32_t)(kt & 1) * ASTAGE_BYTES;
            const size_t ko = base + (size_t)kt * 64 * DK;
#pragma unroll
            for (int i = 0; i < 4; i++) {
                int u = tid + i * 128;        // 0..511
                int row = u >> 3, c16 = u & 7;
                uint32_t so = swz((uint32_t)(row * 128 + c16 * 16));
                cp16(st + so,        g_Kh + ko + (size_t)row * DK + c16 * 8);
                cp16(st + 8192 + so, g_Vh + ko + (size_t)row * DK + c16 * 8);
            }
        };

        // Prologue: Qh parked in stage 1 (8KB), kv0 -> stage 0; one group.
        const uint32_t sQh = sb + ASTAGE_BYTES;
#pragma unroll
        for (int i = 0; i < 4; i++) {
            int u = tid + i * 128;            // 0..511
            int row = u >> 3, c16 = u & 7;
            uint32_t so = swz((uint32_t)(row * 128 + c16 * 16));
            cp16(sQh + so, g_Qh + base + (size_t)(q0 + row) * DK + c16 * 8);
        }
        load_kv(0);
        CP_COMMIT();
        CP_WAIT0();
        __syncthreads();

        uint32_t qh[4][4];
        {
            int r = wid * 16 + (lane & 15);
            uint32_t half = (uint32_t)((lane >> 4) << 4);
#pragma unroll
            for (int kc = 0; kc < 4; kc++)
                ldsm4(qh[kc], sQh + swz((uint32_t)(r * 128 + kc * 32) + half));
        }
        __syncthreads();   // Q reads done before stage 1 reloads

        float o[8][4];
#pragma unroll
        for (int nt = 0; nt < 8; nt++)
#pragma unroll
            for (int q = 0; q < 4; q++) o[nt][q] = 0.f;
        float m0v = -3.0e38f, m1v = -3.0e38f, l0 = 0.f, l1 = 0.f;

        const int rq = q0 + wid * 16 + (lane >> 2);

        for (int kt = 0; kt < nkt; kt++) {
            if (kt > 0) {
                CP_WAIT0();
                __syncthreads();
            }
            if (kt + 1 < nkt) { load_kv(kt + 1); CP_COMMIT(); }

            const uint32_t st = sb + (uint32_t)(kt & 1) * ASTAGE_BYTES;

            // ---- S[64q x 64k] = Qh·Kh ----
            float s[8][4];
#pragma unroll
            for (int nt = 0; nt < 8; nt++)
#pragma unroll
                for (int q = 0; q < 4; q++) s[nt][q] = 0.f;

#pragma unroll
            for (int kc = 0; kc < 4; kc++) {
                uint32_t kb[16];
#pragma unroll
                for (int nb = 0; nb < 4; nb++)
                    ldsm4(kb + nb * 4, st + swz((uint32_t)((nb * 16 + nrow) * 128 + kc * 32) + koff));
#pragma unroll
                for (int nt = 0; nt < 8; nt++) mma16816(s[nt], qh[kc], &kb[nt * 2]);
            }

            // ---- causal mask (diagonal tile only) ----
            if (kt == qi) {
                const int cb = kt * 64 + 2 * (lane & 3);
#pragma unroll
                for (int nt = 0; nt < 8; nt++) {
                    int c0 = cb + 8 * nt;
                    if (c0     > rq)     s[nt][0] = -1.0e30f;
                    if (c0 + 1 > rq)     s[nt][1] = -1.0e30f;
                    if (c0     > rq + 8) s[nt][2] = -1.0e30f;
                    if (c0 + 1 > rq + 8) s[nt][3] = -1.0e30f;
                }
            }

            // ---- online softmax ----
            float mx0 = -3.0e38f, mx1 = -3.0e38f;
#pragma unroll
            for (int nt = 0; nt < 8; nt++) {
                mx0 = fmaxf(mx0, fmaxf(s[nt][0], s[nt][1]));
                mx1 = fmaxf(mx1, fmaxf(s[nt][2], s[nt][3]));
            }
            mx0 = fmaxf(mx0, __shfl_xor_sync(0xFFFFFFFFu, mx0, 1));
            mx0 = fmaxf(mx0, __shfl_xor_sync(0xFFFFFFFFu, mx0, 2));
            mx1 = fmaxf(mx1, __shfl_xor_sync(0xFFFFFFFFu, mx1, 1));
            mx1 = fmaxf(mx1, __shfl_xor_sync(0xFFFFFFFFu, mx1, 2));
            const float mn0 = fmaxf(m0v, mx0), mn1 = fmaxf(m1v, mx1);
            const float f0 = exp2f_fast(m0v - mn0), f1 = exp2f_fast(m1v - mn1);
            m0v = mn0; m1v = mn1;

            float sum0 = 0.f, sum1 = 0.f;
            uint32_t ph[4][4];
#pragma unroll
            for (int kc = 0; kc < 4; kc++) {
                float e00 = exp2f_fast(s[2*kc][0]   - mn0);
                float e01 = exp2f_fast(s[2*kc][1]   - mn0);
                float e10 = exp2f_fast(s[2*kc][2]   - mn1);
                float e11 = exp2f_fast(s[2*kc][3]   - mn1);
                float e20 = exp2f_fast(s[2*kc+1][0] - mn0);
                float e21 = exp2f_fast(s[2*kc+1][1] - mn0);
                float e30 = exp2f_fast(s[2*kc+1][2] - mn1);
                float e31 = exp2f_fast(s[2*kc+1][3] - mn1);
                sum0 += (e00 + e01) + (e20 + e21);
                sum1 += (e10 + e11) + (e30 + e31);
                ph[kc][0] = pack2(e00, e01);
                ph[kc][1] = pack2(e10, e11);
                ph[kc][2] = pack2(e20, e21);
                ph[kc][3] = pack2(e30, e31);
            }
            sum0 += __shfl_xor_sync(0xFFFFFFFFu, sum0, 1);
            sum0 += __shfl_xor_sync(0xFFFFFFFFu, sum0, 2);
            sum1 += __shfl_xor_sync(0xFFFFFFFFu, sum1, 1);
            sum1 += __shfl_xor_sync(0xFFFFFFFFu, sum1, 2);
            l0 = l0 * f0 + sum0;
            l1 = l1 * f1 + sum1;

#pragma unroll
            for (int nt = 0; nt < 8; nt++) {
                o[nt][0] *= f0; o[nt][1] *= f0;
                o[nt][2] *= f1; o[nt][3] *= f1;
            }

            // ---- O += Ph·Vh ----
            const uint32_t stv = st + 8192;
#pragma unroll
            for (int kc = 0; kc < 4; kc++) {
                uint32_t vb[16];
#pragma unroll
                for (int p4 = 0; p4 < 4; p4++)
                    ldsm4t(vb + p4 * 4, stv +
                           swz((uint32_t)((kc * 16 + vkey) * 128 + p4 * 32) + vdk));
#pragma unroll
                for (int nt = 0; nt < 8; nt++) mma16816(o[nt], ph[kc], &vb[nt * 2]);
            }
        }

        // ---- epilogue: normalize, store fp16 hi to [B,S,H*DK] ----
        const float inv0 = 1.0f / l0, inv1 = 1.0f / l1;
#pragma unroll
        for (int nt = 0; nt < 8; nt++) {
            const int d = hd * 64 + dkb + 8 * nt;
            size_t i0 = ((size_t)b * SEQ + rq) * DMODEL + d;
            size_t i1 = ((size_t)b * SEQ + rq + 8) * DMODEL + d;
            uint32_t p0 = pack2(o[nt][0] * inv0, o[nt][1] * inv0);
            uint32_t p1 = pack2(o[nt][2] * inv1, o[nt][3] * inv1);
            *reinterpret_cast<uint32_t*>(g_ah + i0) = p0;
            *reinterpret_cast<uint32_t*>(g_ah + i1) = p1;
        }
        __syncthreads();   // smem quiescent before next part's prologue
    }
}

// ---------------------------------------------------------------------------
extern "C" void kernel_launch(void* const* d_in, const int* in_sizes, int n_in,
                              void* d_out, int out_size)
{
    const float* x  = (const float*)d_in[0];
    const float* Wq = (const float*)d_in[1];
    const float* bq = (const float*)d_in[2];
    const float* Wk = (const float*)d_in[3];
    const float* bk = (const float*)d_in[4];
    const float* Wv = (const float*)d_in[5];
    const float* bv = (const float*)d_in[6];
    const float* Wo = (const float*)d_in[7];
    const float* bo = (const float*)d_in[8];
    float* out = (float*)d_out;
    (void)in_sizes; (void)n_in; (void)out_size;

    static bool attr_done = false;
    if (!attr_done) {
        cudaFuncSetAttribute(mma_gemm<0>, cudaFuncAttributeMaxDynamicSharedMemorySize, GEMM_SMEM);
        cudaFuncSetAttribute(mma_gemm<1>, cudaFuncAttributeMaxDynamicSharedMemorySize, GEMM_SMEM);
        cudaFuncSetAttribute(attn_mma_kernel, cudaFuncAttributeMaxDynamicSharedMemorySize, ATTN_SMEM);
        attr_done = true;
    }

    split_all_kernel<<<SPLIT_BLOCKS, 256>>>((const float4*)x, (const float4*)Wq,
                                            (const float4*)Wk, (const float4*)Wv,
                                            (const float4*)Wo);

    dim3 gQKV(MTOT / BM, DMODEL / BN, 3);
    mma_gemm<0><<<gQKV, 256, GEMM_SMEM>>>(bq, bk, bv, nullptr);

    dim3 gAttn(NQT / 2, BATCH * NHEADS);
    attn_mma_kernel<<<gAttn, 128, ATTN_SMEM>>>();

    dim3 gProj(MTOT / BM, DMODEL / BN);
    mma_gemm<1><<<gProj, 256, GEMM_SMEM>>>(bo, nullptr, nullptr, out);
}